// round 4
// baseline (speedup 1.0000x reference)
#include <cuda_runtime.h>
#include <cuda_bf16.h>
#include <mma.h>
#include <cstdint>

using namespace nvcuda;

#define Bb 32
#define Nn 4096
#define Mm 512
#define Cc 256

// ---------------------------------------------------------------------------
// Global scratch (static __device__ — no runtime allocation)
// ---------------------------------------------------------------------------
__device__ __align__(16) __nv_bfloat16 g_Ach[Mm * Nn];
__device__ __align__(16) __nv_bfloat16 g_Acl[Mm * Nn];
__device__ __align__(16) __nv_bfloat16 g_Ash[Mm * Nn];   // holds -sin hi
__device__ __align__(16) __nv_bfloat16 g_Asl[Mm * Nn];   // holds -sin lo
__device__ __align__(16) __nv_bfloat16 g_AinvH[Nn * 2 * Mm];
__device__ __align__(16) __nv_bfloat16 g_AinvL[Nn * 2 * Mm];
__device__ __align__(16) __nv_bfloat16 g_Vh[(size_t)Bb * Nn * Cc];
__device__ __align__(16) __nv_bfloat16 g_Vl[(size_t)Bb * Nn * Cc];
__device__ __align__(16) __nv_bfloat16 g_Gh[(size_t)Bb * 2 * Mm * Cc];
__device__ __align__(16) __nv_bfloat16 g_Gl[(size_t)Bb * 2 * Mm * Cc];
__device__ float d_Fre[Bb * Mm * Cc];
__device__ float d_Fim[Bb * Mm * Cc];
__device__ float d_Gre[Bb * Mm * Cc];
__device__ float d_Gim[Bb * Mm * Cc];

// ---------------------------------------------------------------------------
__device__ __forceinline__ uint32_t s2u(const void* p) {
    uint32_t a;
    asm("{ .reg .u64 t; cvta.to.shared.u64 t, %1; cvt.u32.u64 %0, t; }"
        : "=r"(a) : "l"(p));
    return a;
}

#define CP16(dst, src) \
    asm volatile("cp.async.cg.shared.global [%0], [%1], 16;" :: "r"(dst), "l"(src))
#define CP_COMMIT() asm volatile("cp.async.commit_group;")
#define CP_WAIT1()  asm volatile("cp.async.wait_group 1;" ::: "memory")
#define CP_WAIT0()  asm volatile("cp.async.wait_group 0;" ::: "memory")

__device__ __forceinline__ void split_bf16(float x, __nv_bfloat16& hi, __nv_bfloat16& lo) {
    hi = __float2bfloat16(x);
    lo = __float2bfloat16(x - __bfloat162float(hi));
}

typedef wmma::fragment<wmma::matrix_a, 16, 16, 16, __nv_bfloat16, wmma::row_major> FragA;
typedef wmma::fragment<wmma::matrix_b, 16, 16, 16, __nv_bfloat16, wmma::row_major> FragB;
typedef wmma::fragment<wmma::accumulator, 16, 16, 16, float> FragC;

// ---------------------------------------------------------------------------
// Prep kernels
// ---------------------------------------------------------------------------
__global__ __launch_bounds__(256) void genA_fwd() {
    int idx = blockIdx.x * blockDim.x + threadIdx.x;
    if (idx >= Mm * Nn) return;
    int m = idx >> 12, n = idx & (Nn - 1);
    int t = (int)(((long long)m * n) & (Nn - 1));
    float s, c;
    sincospif((float)t * (1.0f / 2048.0f), &s, &c);
    __nv_bfloat16 h, l;
    split_bf16(c, h, l);
    g_Ach[idx] = h; g_Acl[idx] = l;
    split_bf16(-s, h, l);
    g_Ash[idx] = h; g_Asl[idx] = l;
}

__global__ __launch_bounds__(256) void genA_inv() {
    int idx = blockIdx.x * blockDim.x + threadIdx.x;
    if (idx >= Nn * 2 * Mm) return;
    int n = idx >> 10, mp = idx & 1023;
    int m = (mp < Mm) ? mp : (mp - Mm);
    int t = (int)(((long long)m * n) & (Nn - 1));
    float s, c;
    sincospif((float)t * (1.0f / 2048.0f), &s, &c);
    float val = (mp < Mm) ? c : s;
    __nv_bfloat16 h, l;
    split_bf16(val, h, l);
    g_AinvH[idx] = h; g_AinvL[idx] = l;
}

__global__ __launch_bounds__(256) void packV(const float* __restrict__ v) {
    size_t i4 = (size_t)blockIdx.x * blockDim.x + threadIdx.x;
    size_t base = i4 * 4;
    if (base >= (size_t)Bb * Nn * Cc) return;
    float4 x = *(const float4*)(v + base);
    __nv_bfloat16 h0, l0, h1, l1, h2, l2, h3, l3;
    split_bf16(x.x, h0, l0); split_bf16(x.y, h1, l1);
    split_bf16(x.z, h2, l2); split_bf16(x.w, h3, l3);
    *(__nv_bfloat162*)(g_Vh + base)     = __nv_bfloat162{h0, h1};
    *(__nv_bfloat162*)(g_Vh + base + 2) = __nv_bfloat162{h2, h3};
    *(__nv_bfloat162*)(g_Vl + base)     = __nv_bfloat162{l0, l1};
    *(__nv_bfloat162*)(g_Vl + base + 2) = __nv_bfloat162{l2, l3};
}

__global__ __launch_bounds__(256) void pack_G() {
    size_t i4 = (size_t)blockIdx.x * blockDim.x + threadIdx.x;
    size_t base = i4 * 4;
    if (base >= (size_t)Bb * 2 * Mm * Cc) return;
    int b = (int)(base >> 18);
    int rem = (int)(base & 262143);
    int mp = rem >> 8, o = rem & 255;
    float4 x;
    if (mp < Mm) {
        x = *(const float4*)(d_Gre + ((size_t)b * Mm + mp) * Cc + o);
    } else {
        float4 gi = *(const float4*)(d_Gim + ((size_t)b * Mm + (mp - Mm)) * Cc + o);
        x = make_float4(-gi.x, -gi.y, -gi.z, -gi.w);
    }
    __nv_bfloat16 h0, l0, h1, l1, h2, l2, h3, l3;
    split_bf16(x.x, h0, l0); split_bf16(x.y, h1, l1);
    split_bf16(x.z, h2, l2); split_bf16(x.w, h3, l3);
    *(__nv_bfloat162*)(g_Gh + base)     = __nv_bfloat162{h0, h1};
    *(__nv_bfloat162*)(g_Gh + base + 2) = __nv_bfloat162{h2, h3};
    *(__nv_bfloat162*)(g_Gl + base)     = __nv_bfloat162{l0, l1};
    *(__nv_bfloat162*)(g_Gl + base + 2) = __nv_bfloat162{l2, l3};
}

// ---------------------------------------------------------------------------
// Forward WMMA GEMM. CTA 128(m) x 128(i), 512 threads (16 warps, 4x4 of 32x32),
// K=4096 in 32-wide double-buffered cp.async chunks.
// ---------------------------------------------------------------------------
#define STAGE_FWD 58368

__device__ __forceinline__ void fwd_load(uint32_t sbase, int m0, int i0, int b,
                                         int k0, int tid) {
    int r = tid >> 2, s4 = tid & 3;
    size_t aoff = (size_t)(m0 + r) * Nn + k0 + s4 * 8;
    uint32_t ad = sbase + r * 80 + s4 * 16;
    CP16(ad,         g_Ach + aoff);
    CP16(ad + 10240, g_Acl + aoff);
    CP16(ad + 20480, g_Ash + aoff);
    CP16(ad + 30720, g_Asl + aoff);
    int kr = tid >> 4, s16 = tid & 15;
    size_t boff = ((size_t)b * Nn + k0 + kr) * Cc + i0 + s16 * 8;
    uint32_t bd = sbase + 40960 + kr * 272 + s16 * 16;
    CP16(bd,        g_Vh + boff);
    CP16(bd + 8704, g_Vl + boff);
    CP_COMMIT();
}

__global__ __launch_bounds__(512) void fwd_gemm() {
    extern __shared__ __align__(16) char sm[];
    const uint32_t sb = s2u(sm);
    const int tid = threadIdx.x;
    const int warpId = tid >> 5;
    const int wm = warpId >> 2, wi = warpId & 3;
    const int it = blockIdx.x, mt = blockIdx.y, b = blockIdx.z;
    const int m0 = mt * 128, i0 = it * 128;

    FragC accR[2][2], accI[2][2];
    #pragma unroll
    for (int a = 0; a < 2; a++)
        #pragma unroll
        for (int c = 0; c < 2; c++) {
            wmma::fill_fragment(accR[a][c], 0.0f);
            wmma::fill_fragment(accI[a][c], 0.0f);
        }

    fwd_load(sb, m0, i0, b, 0, tid);

    const int NCH = Nn / 32;
    for (int c = 0; c < NCH; c++) {
        int buf = c & 1;
        if (c + 1 < NCH) {
            fwd_load(sb + (buf ^ 1) * STAGE_FWD, m0, i0, b, (c + 1) * 32, tid);
            CP_WAIT1();
        } else {
            CP_WAIT0();
        }
        __syncthreads();

        const char* base = sm + buf * STAGE_FWD;
        const __nv_bfloat16* Ach = (const __nv_bfloat16*)(base);
        const __nv_bfloat16* Acl = (const __nv_bfloat16*)(base + 10240);
        const __nv_bfloat16* Ash = (const __nv_bfloat16*)(base + 20480);
        const __nv_bfloat16* Asl = (const __nv_bfloat16*)(base + 30720);
        const __nv_bfloat16* Bvh = (const __nv_bfloat16*)(base + 40960);
        const __nv_bfloat16* Bvl = (const __nv_bfloat16*)(base + 49664);

        #pragma unroll
        for (int ks = 0; ks < 2; ks++) {
            const int kk = ks * 16;
            FragB vh[2], vl[2];
            #pragma unroll
            for (int is_ = 0; is_ < 2; is_++) {
                wmma::load_matrix_sync(vh[is_], Bvh + kk * 136 + wi * 32 + is_ * 16, 136);
                wmma::load_matrix_sync(vl[is_], Bvl + kk * 136 + wi * 32 + is_ * 16, 136);
            }
            #pragma unroll
            for (int ms = 0; ms < 2; ms++) {
                const int ao = (wm * 32 + ms * 16) * 40 + kk;
                FragA ach, acl, ash, asl;
                wmma::load_matrix_sync(ach, Ach + ao, 40);
                wmma::load_matrix_sync(acl, Acl + ao, 40);
                wmma::load_matrix_sync(ash, Ash + ao, 40);
                wmma::load_matrix_sync(asl, Asl + ao, 40);
                #pragma unroll
                for (int is_ = 0; is_ < 2; is_++) {
                    wmma::mma_sync(accR[ms][is_], ach, vh[is_], accR[ms][is_]);
                    wmma::mma_sync(accR[ms][is_], ach, vl[is_], accR[ms][is_]);
                    wmma::mma_sync(accR[ms][is_], acl, vh[is_], accR[ms][is_]);
                    wmma::mma_sync(accI[ms][is_], ash, vh[is_], accI[ms][is_]);
                    wmma::mma_sync(accI[ms][is_], ash, vl[is_], accI[ms][is_]);
                    wmma::mma_sync(accI[ms][is_], asl, vh[is_], accI[ms][is_]);
                }
            }
        }
        __syncthreads();
    }

    #pragma unroll
    for (int ms = 0; ms < 2; ms++)
        #pragma unroll
        for (int is_ = 0; is_ < 2; is_++) {
            size_t off = ((size_t)b * Mm + m0 + wm * 32 + ms * 16) * Cc
                         + i0 + wi * 32 + is_ * 16;
            wmma::store_matrix_sync(d_Fre + off, accR[ms][is_], Cc, wmma::mem_row_major);
            wmma::store_matrix_sync(d_Fim + off, accI[ms][is_], Cc, wmma::mem_row_major);
        }
}

// ---------------------------------------------------------------------------
// Mid (fp32): G[b,m,o] = (w_m/N) * sum_i R[m,i,o] * F[b,m,i]
// ---------------------------------------------------------------------------
__global__ __launch_bounds__(256) void mid_kernel(const float* __restrict__ R) {
    __shared__ float Are[16][34];
    __shared__ float Aim[16][34];
    __shared__ float Bs[16][64];

    const int m = blockIdx.y;
    const int o0 = blockIdx.x * 64;
    const int tid = threadIdx.x;
    const int tx = tid & 15, ty = tid >> 4;

    float ar[2][4] = {}, ai[2][4] = {};
    const float* Rm = R + (size_t)m * Cc * Cc;
    const int la_c = tid & 15, la_r0 = tid >> 4;
    const int lb_c = tid & 63, lb_r0 = tid >> 6;

    for (int k0 = 0; k0 < Cc; k0 += 16) {
        #pragma unroll
        for (int i = 0; i < 2; i++) {
            int r = la_r0 + i * 16;
            size_t g = (size_t)r * Mm * Cc + (size_t)m * Cc + (k0 + la_c);
            Are[la_c][r] = d_Fre[g];
            Aim[la_c][r] = d_Fim[g];
        }
        #pragma unroll
        for (int i = 0; i < 4; i++) {
            int r = lb_r0 + i * 4;
            Bs[r][lb_c] = Rm[(size_t)(k0 + r) * Cc + o0 + lb_c];
        }
        __syncthreads();
        #pragma unroll
        for (int k = 0; k < 16; k++) {
            float are0 = Are[k][ty * 2], are1 = Are[k][ty * 2 + 1];
            float aim0 = Aim[k][ty * 2], aim1 = Aim[k][ty * 2 + 1];
            float4 b4 = *(const float4*)&Bs[k][tx * 4];
            float bv[4] = {b4.x, b4.y, b4.z, b4.w};
            #pragma unroll
            for (int j = 0; j < 4; j++) {
                ar[0][j] += are0 * bv[j];
                ar[1][j] += are1 * bv[j];
                ai[0][j] += aim0 * bv[j];
                ai[1][j] += aim1 * bv[j];
            }
        }
        __syncthreads();
    }
    const float scale = (m == 0) ? (1.0f / Nn) : (2.0f / Nn);
    #pragma unroll
    for (int i = 0; i < 2; i++) {
        int bidx = ty * 2 + i;
        size_t base = (size_t)bidx * Mm * Cc + (size_t)m * Cc + o0 + tx * 4;
        float4 re = make_float4(scale * ar[i][0], scale * ar[i][1], scale * ar[i][2], scale * ar[i][3]);
        float4 im = make_float4(scale * ai[i][0], scale * ai[i][1], scale * ai[i][2], scale * ai[i][3]);
        *(float4*)&d_Gre[base] = re;
        *(float4*)&d_Gim[base] = im;
    }
}

// ---------------------------------------------------------------------------
// Inverse WMMA GEMM. CTA 128(n) x 128(o), K = 1024 (cos|sin concat).
// ---------------------------------------------------------------------------
#define STAGE_INV 37888

__device__ __forceinline__ void inv_load(uint32_t sbase, int n0, int o0, int b,
                                         int k0, int tid) {
    int r = tid >> 2, s4 = tid & 3;
    size_t aoff = (size_t)(n0 + r) * 1024 + k0 + s4 * 8;
    uint32_t ad = sbase + r * 80 + s4 * 16;
    CP16(ad,         g_AinvH + aoff);
    CP16(ad + 10240, g_AinvL + aoff);
    int kr = tid >> 4, s16 = tid & 15;
    size_t boff = ((size_t)b * 1024 + k0 + kr) * Cc + o0 + s16 * 8;
    uint32_t bd = sbase + 20480 + kr * 272 + s16 * 16;
    CP16(bd,        g_Gh + boff);
    CP16(bd + 8704, g_Gl + boff);
    CP_COMMIT();
}

__global__ __launch_bounds__(512) void inv_gemm(const float* __restrict__ v,
                                                float* __restrict__ out) {
    extern __shared__ __align__(16) char sm[];
    const uint32_t sb = s2u(sm);
    const int tid = threadIdx.x;
    const int warpId = tid >> 5;
    const int wm = warpId >> 2, wi = warpId & 3;
    const int ot = blockIdx.x, nt = blockIdx.y, b = blockIdx.z;
    const int n0 = nt * 128, o0 = ot * 128;

    FragC acc[2][2];
    #pragma unroll
    for (int a = 0; a < 2; a++)
        #pragma unroll
        for (int c = 0; c < 2; c++) wmma::fill_fragment(acc[a][c], 0.0f);

    inv_load(sb, n0, o0, b, 0, tid);

    const int NCH = 1024 / 32;
    for (int c = 0; c < NCH; c++) {
        int buf = c & 1;
        if (c + 1 < NCH) {
            inv_load(sb + (buf ^ 1) * STAGE_INV, n0, o0, b, (c + 1) * 32, tid);
            CP_WAIT1();
        } else {
            CP_WAIT0();
        }
        __syncthreads();

        const char* base = sm + buf * STAGE_INV;
        const __nv_bfloat16* Ah = (const __nv_bfloat16*)(base);
        const __nv_bfloat16* Al = (const __nv_bfloat16*)(base + 10240);
        const __nv_bfloat16* Bh = (const __nv_bfloat16*)(base + 20480);
        const __nv_bfloat16* Bl = (const __nv_bfloat16*)(base + 29184);

        #pragma unroll
        for (int ks = 0; ks < 2; ks++) {
            const int kk = ks * 16;
            FragB gh[2], gl[2];
            #pragma unroll
            for (int is_ = 0; is_ < 2; is_++) {
                wmma::load_matrix_sync(gh[is_], Bh + kk * 136 + wi * 32 + is_ * 16, 136);
                wmma::load_matrix_sync(gl[is_], Bl + kk * 136 + wi * 32 + is_ * 16, 136);
            }
            #pragma unroll
            for (int ms = 0; ms < 2; ms++) {
                const int ao = (wm * 32 + ms * 16) * 40 + kk;
                FragA ah, al;
                wmma::load_matrix_sync(ah, Ah + ao, 40);
                wmma::load_matrix_sync(al, Al + ao, 40);
                #pragma unroll
                for (int is_ = 0; is_ < 2; is_++) {
                    wmma::mma_sync(acc[ms][is_], ah, gh[is_], acc[ms][is_]);
                    wmma::mma_sync(acc[ms][is_], ah, gl[is_], acc[ms][is_]);
                    wmma::mma_sync(acc[ms][is_], al, gh[is_], acc[ms][is_]);
                }
            }
        }
        __syncthreads();
    }

    float* bounce = (float*)sm;
    #pragma unroll
    for (int ms = 0; ms < 2; ms++)
        #pragma unroll
        for (int is_ = 0; is_ < 2; is_++)
            wmma::store_matrix_sync(bounce + (wm * 32 + ms * 16) * 136 + wi * 32 + is_ * 16,
                                    acc[ms][is_], 136, wmma::mem_row_major);
    __syncthreads();
    #pragma unroll
    for (int j = 0; j < 8; j++) {
        int idx4 = tid + 512 * j;
        int row = idx4 >> 5, c4 = idx4 & 31;
        float4 bv = *(const float4*)(bounce + row * 136 + c4 * 4);
        size_t a = ((size_t)b * Nn + n0 + row) * Cc + o0 + c4 * 4;
        float4 vv = *(const float4*)(v + a);
        *(float4*)(out + a) = make_float4(vv.x + bv.x, vv.y + bv.y,
                                          vv.z + bv.z, vv.w + bv.w);
    }
}

// ---------------------------------------------------------------------------
extern "C" void kernel_launch(void* const* d_in, const int* in_sizes, int n_in,
                              void* d_out, int out_size) {
    const float* v = (const float*)d_in[0];
    const float* R = (const float*)d_in[1];
    float* out = (float*)d_out;

    const int smF = 2 * STAGE_FWD;
    const int smI = 2 * STAGE_INV;
    cudaFuncSetAttribute(fwd_gemm, cudaFuncAttributeMaxDynamicSharedMemorySize, smF);
    cudaFuncSetAttribute(inv_gemm, cudaFuncAttributeMaxDynamicSharedMemorySize, smI);

    genA_fwd<<<(Mm * Nn) / 256, 256>>>();
    genA_inv<<<(Nn * 2 * Mm) / 256, 256>>>();
    packV<<<(int)(((size_t)Bb * Nn * Cc / 4) / 256), 256>>>(v);
    fwd_gemm<<<dim3(2, 4, 32), 512, smF>>>();
    mid_kernel<<<dim3(Cc / 64, Mm), 256>>>(R);
    pack_G<<<(int)(((size_t)Bb * 2 * Mm * Cc / 4) / 256), 256>>>();
    inv_gemm<<<dim3(2, 32, 32), 512, smI>>>(v, out);
}

// round 5
// speedup vs baseline: 1.3949x; 1.3949x over previous
#include <cuda_runtime.h>
#include <cuda_bf16.h>
#include <mma.h>
#include <cstdint>

using namespace nvcuda;

#define Bb 32
#define Nn 4096
#define Mm 512
#define Cc 256
#define KF 2080            // folded forward K (0..2048 data, padded to 32*65)
#define NH 2048            // half length for inverse rows

// ---------------------------------------------------------------------------
// Global scratch (static __device__ — no runtime allocation)
// ---------------------------------------------------------------------------
// Forward twiddles: [512][KF]  cos hi/lo, (-sin) hi/lo
__device__ __align__(16) __nv_bfloat16 g_AcosH[Mm * KF];
__device__ __align__(16) __nv_bfloat16 g_AcosL[Mm * KF];
__device__ __align__(16) __nv_bfloat16 g_AsinH[Mm * KF];
__device__ __align__(16) __nv_bfloat16 g_AsinL[Mm * KF];
// Folded v: vp = v[k]+v[N-k], vm = v[k]-v[N-k]; [b][KF][256]
__device__ __align__(16) __nv_bfloat16 g_VpH[(size_t)Bb * KF * Cc];
__device__ __align__(16) __nv_bfloat16 g_VpL[(size_t)Bb * KF * Cc];
__device__ __align__(16) __nv_bfloat16 g_VmH[(size_t)Bb * KF * Cc];
__device__ __align__(16) __nv_bfloat16 g_VmL[(size_t)Bb * KF * Cc];
// Inverse twiddles: [2048 n][512 m]  cos hi/lo, sin hi/lo
__device__ __align__(16) __nv_bfloat16 g_icosH[NH * Mm];
__device__ __align__(16) __nv_bfloat16 g_icosL[NH * Mm];
__device__ __align__(16) __nv_bfloat16 g_isinH[NH * Mm];
__device__ __align__(16) __nv_bfloat16 g_isinL[NH * Mm];
// Split scaled spectra: [b][512][256]
__device__ __align__(16) __nv_bfloat16 g_GreH[(size_t)Bb * Mm * Cc];
__device__ __align__(16) __nv_bfloat16 g_GreL[(size_t)Bb * Mm * Cc];
__device__ __align__(16) __nv_bfloat16 g_GimH[(size_t)Bb * Mm * Cc];
__device__ __align__(16) __nv_bfloat16 g_GimL[(size_t)Bb * Mm * Cc];
// fp32 intermediates
__device__ float d_Fre[Bb * Mm * Cc];
__device__ float d_Fim[Bb * Mm * Cc];
__device__ float d_Gre[Bb * Mm * Cc];
__device__ float d_Gim[Bb * Mm * Cc];
// Inverse half-spectrum results: [b][2048][256]
__device__ float d_C[(size_t)Bb * NH * Cc];
__device__ float d_S[(size_t)Bb * NH * Cc];

// ---------------------------------------------------------------------------
__device__ __forceinline__ uint32_t s2u(const void* p) {
    uint32_t a;
    asm("{ .reg .u64 t; cvta.to.shared.u64 t, %1; cvt.u32.u64 %0, t; }"
        : "=r"(a) : "l"(p));
    return a;
}

#define CP16(dst, src) \
    asm volatile("cp.async.cg.shared.global [%0], [%1], 16;" :: "r"(dst), "l"(src))
#define CP_COMMIT() asm volatile("cp.async.commit_group;")
#define CP_WAIT2()  asm volatile("cp.async.wait_group 2;" ::: "memory")
#define CP_WAIT1()  asm volatile("cp.async.wait_group 1;" ::: "memory")
#define CP_WAIT0()  asm volatile("cp.async.wait_group 0;" ::: "memory")

__device__ __forceinline__ void split_bf16(float x, __nv_bfloat16& hi, __nv_bfloat16& lo) {
    hi = __float2bfloat16(x);
    lo = __float2bfloat16(x - __bfloat162float(hi));
}

typedef wmma::fragment<wmma::matrix_a, 16, 16, 16, __nv_bfloat16, wmma::row_major> FragA;
typedef wmma::fragment<wmma::matrix_b, 16, 16, 16, __nv_bfloat16, wmma::row_major> FragB;
typedef wmma::fragment<wmma::accumulator, 16, 16, 16, float> FragC;

// ---------------------------------------------------------------------------
// Prep kernels
// ---------------------------------------------------------------------------
__global__ __launch_bounds__(256) void genA_fwd() {
    int idx = blockIdx.x * blockDim.x + threadIdx.x;
    if (idx >= Mm * KF) return;
    int m = idx / KF, k = idx - m * KF;
    int t = (int)(((long long)m * k) & (Nn - 1));
    float s, c;
    sincospif((float)t * (1.0f / 2048.0f), &s, &c);
    __nv_bfloat16 h, l;
    split_bf16(c, h, l);
    g_AcosH[idx] = h; g_AcosL[idx] = l;
    split_bf16(-s, h, l);
    g_AsinH[idx] = h; g_AsinL[idx] = l;
}

__global__ __launch_bounds__(256) void genA_inv() {
    int idx = blockIdx.x * blockDim.x + threadIdx.x;
    if (idx >= NH * Mm) return;
    int n = idx >> 9, m = idx & 511;
    int t = (int)(((long long)m * n) & (Nn - 1));
    float s, c;
    sincospif((float)t * (1.0f / 2048.0f), &s, &c);
    __nv_bfloat16 h, l;
    split_bf16(c, h, l);
    g_icosH[idx] = h; g_icosL[idx] = l;
    split_bf16(s, h, l);
    g_isinH[idx] = h; g_isinL[idx] = l;
}

// Fold + split v.  idx4 over [b][KF][256/4]
__global__ __launch_bounds__(256) void packVpVm(const float* __restrict__ v) {
    size_t idx4 = (size_t)blockIdx.x * blockDim.x + threadIdx.x;
    if (idx4 >= (size_t)Bb * KF * 64) return;
    int b = (int)(idx4 / (KF * 64));
    int rem = (int)(idx4 - (size_t)b * (KF * 64));
    int k = rem >> 6, i = (rem & 63) * 4;
    float4 vp, vm;
    if (k == 0) {
        vp = *(const float4*)(v + ((size_t)b * Nn) * Cc + i);
        vm = make_float4(0.f, 0.f, 0.f, 0.f);
    } else if (k < 2048) {
        float4 a = *(const float4*)(v + ((size_t)b * Nn + k) * Cc + i);
        float4 c = *(const float4*)(v + ((size_t)b * Nn + (Nn - k)) * Cc + i);
        vp = make_float4(a.x + c.x, a.y + c.y, a.z + c.z, a.w + c.w);
        vm = make_float4(a.x - c.x, a.y - c.y, a.z - c.z, a.w - c.w);
    } else if (k == 2048) {
        vp = *(const float4*)(v + ((size_t)b * Nn + 2048) * Cc + i);
        vm = make_float4(0.f, 0.f, 0.f, 0.f);
    } else {
        vp = make_float4(0.f, 0.f, 0.f, 0.f);
        vm = vp;
    }
    size_t base = ((size_t)b * KF + k) * Cc + i;
    __nv_bfloat16 h0, l0, h1, l1, h2, l2, h3, l3;
    split_bf16(vp.x, h0, l0); split_bf16(vp.y, h1, l1);
    split_bf16(vp.z, h2, l2); split_bf16(vp.w, h3, l3);
    *(__nv_bfloat162*)(g_VpH + base)     = __nv_bfloat162{h0, h1};
    *(__nv_bfloat162*)(g_VpH + base + 2) = __nv_bfloat162{h2, h3};
    *(__nv_bfloat162*)(g_VpL + base)     = __nv_bfloat162{l0, l1};
    *(__nv_bfloat162*)(g_VpL + base + 2) = __nv_bfloat162{l2, l3};
    split_bf16(vm.x, h0, l0); split_bf16(vm.y, h1, l1);
    split_bf16(vm.z, h2, l2); split_bf16(vm.w, h3, l3);
    *(__nv_bfloat162*)(g_VmH + base)     = __nv_bfloat162{h0, h1};
    *(__nv_bfloat162*)(g_VmH + base + 2) = __nv_bfloat162{h2, h3};
    *(__nv_bfloat162*)(g_VmL + base)     = __nv_bfloat162{l0, l1};
    *(__nv_bfloat162*)(g_VmL + base + 2) = __nv_bfloat162{l2, l3};
}

// Split scaled G.
__global__ __launch_bounds__(256) void pack_G() {
    size_t idx4 = (size_t)blockIdx.x * blockDim.x + threadIdx.x;
    size_t base = idx4 * 4;
    if (base >= (size_t)Bb * Mm * Cc) return;
    float4 re = *(const float4*)(d_Gre + base);
    float4 im = *(const float4*)(d_Gim + base);
    __nv_bfloat16 h0, l0, h1, l1, h2, l2, h3, l3;
    split_bf16(re.x, h0, l0); split_bf16(re.y, h1, l1);
    split_bf16(re.z, h2, l2); split_bf16(re.w, h3, l3);
    *(__nv_bfloat162*)(g_GreH + base)     = __nv_bfloat162{h0, h1};
    *(__nv_bfloat162*)(g_GreH + base + 2) = __nv_bfloat162{h2, h3};
    *(__nv_bfloat162*)(g_GreL + base)     = __nv_bfloat162{l0, l1};
    *(__nv_bfloat162*)(g_GreL + base + 2) = __nv_bfloat162{l2, l3};
    split_bf16(im.x, h0, l0); split_bf16(im.y, h1, l1);
    split_bf16(im.z, h2, l2); split_bf16(im.w, h3, l3);
    *(__nv_bfloat162*)(g_GimH + base)     = __nv_bfloat162{h0, h1};
    *(__nv_bfloat162*)(g_GimH + base + 2) = __nv_bfloat162{h2, h3};
    *(__nv_bfloat162*)(g_GimL + base)     = __nv_bfloat162{l0, l1};
    *(__nv_bfloat162*)(g_GimL + base + 2) = __nv_bfloat162{l2, l3};
}

// ---------------------------------------------------------------------------
// Unified WMMA GEMM (3-term bf16 split, 3-stage cp.async pipeline).
// CTA 128(rows) x 128(cols), 256 threads, 8 warps, warp tile 32x64.
// mode 0 (fwd):  A [512][KF] twiddles, B [b][KF][256] vp/vm, Out F [b][512][256]
// mode 1 (inv):  A [2048][512],        B [b][512][256] G,     Out C/S [b][2048][256]
// grid: (2, nyt*2, 32);  comp = re/cos vs im/sin.
// Stage layout (37888B): Ah[128][40] @0, Al @10240, Bh[32][136] @20480, Bl @29184
// ---------------------------------------------------------------------------
#define STAGE 37888

__global__ __launch_bounds__(256) void gemm_ws(int mode) {
    extern __shared__ __align__(16) char sm[];
    const uint32_t sb = s2u(sm);
    const int tid = threadIdx.x;
    const int warp = tid >> 5;
    const int wm = warp >> 1, wn = warp & 1;
    const int it = blockIdx.x, b = blockIdx.z;
    const int nyt = mode ? 16 : 4;
    const int y = blockIdx.y;
    const int comp = (y >= nyt) ? 1 : 0;
    const int yt = comp ? (y - nyt) : y;

    const __nv_bfloat16 *Ah, *Al, *Bh, *Bl;
    float* Out;
    int Astride, K, NCH;
    size_t outB;
    if (mode == 0) {
        Astride = KF; K = KF; NCH = KF / 32; outB = (size_t)Mm * Cc;
        if (comp) { Ah = g_AsinH; Al = g_AsinL; Bh = g_VmH; Bl = g_VmL; Out = d_Fim; }
        else      { Ah = g_AcosH; Al = g_AcosL; Bh = g_VpH; Bl = g_VpL; Out = d_Fre; }
    } else {
        Astride = Mm; K = Mm; NCH = Mm / 32; outB = (size_t)NH * Cc;
        if (comp) { Ah = g_isinH; Al = g_isinL; Bh = g_GimH; Bl = g_GimL; Out = d_S; }
        else      { Ah = g_icosH; Al = g_icosL; Bh = g_GreH; Bl = g_GreL; Out = d_C; }
    }
    const int row0 = yt * 128, c0 = it * 128;

    FragC acc[2][4];
    #pragma unroll
    for (int a = 0; a < 2; a++)
        #pragma unroll
        for (int j = 0; j < 4; j++) wmma::fill_fragment(acc[a][j], 0.0f);

    const int lr = tid & 127, lh = tid >> 7;        // A loader
    const int kr = tid >> 3, s8 = tid & 7;          // B loader

    auto load = [&](int stage, int k0) {
        uint32_t s0 = sb + stage * STAGE;
        size_t ga = (size_t)(row0 + lr) * Astride + k0 + lh * 16;
        uint32_t ad = s0 + lr * 80 + lh * 32;
        CP16(ad, Ah + ga);           CP16(ad + 16, Ah + ga + 8);
        CP16(ad + 10240, Al + ga);   CP16(ad + 10256, Al + ga + 8);
        size_t gb = ((size_t)b * K + k0 + kr) * Cc + c0 + s8 * 8;
        uint32_t bd = s0 + 20480 + kr * 272 + s8 * 16;
        CP16(bd, Bh + gb);           CP16(bd + 128, Bh + gb + 64);
        CP16(bd + 8704, Bl + gb);    CP16(bd + 8832, Bl + gb + 64);
        CP_COMMIT();
    };

    load(0, 0);
    load(1, 32);

    int stage = 0;
    for (int c = 0; c < NCH; c++) {
        if (c + 2 < NCH) {
            int ns = stage + 2; if (ns >= 3) ns -= 3;
            load(ns, (c + 2) * 32);
            CP_WAIT2();
        } else if (c + 1 < NCH) {
            CP_WAIT1();
        } else {
            CP_WAIT0();
        }
        __syncthreads();

        const char* base = sm + stage * STAGE;
        const __nv_bfloat16* Ahs = (const __nv_bfloat16*)(base);
        const __nv_bfloat16* Als = (const __nv_bfloat16*)(base + 10240);
        const __nv_bfloat16* Bhs = (const __nv_bfloat16*)(base + 20480);
        const __nv_bfloat16* Bls = (const __nv_bfloat16*)(base + 29184);

        #pragma unroll
        for (int ks = 0; ks < 2; ks++) {
            const int kk = ks * 16;
            FragB bh[4], bl[4];
            #pragma unroll
            for (int j = 0; j < 4; j++) {
                wmma::load_matrix_sync(bh[j], Bhs + kk * 136 + wn * 64 + j * 16, 136);
                wmma::load_matrix_sync(bl[j], Bls + kk * 136 + wn * 64 + j * 16, 136);
            }
            #pragma unroll
            for (int ms = 0; ms < 2; ms++) {
                const int ao = (wm * 32 + ms * 16) * 40 + kk;
                FragA ah, al;
                wmma::load_matrix_sync(ah, Ahs + ao, 40);
                wmma::load_matrix_sync(al, Als + ao, 40);
                #pragma unroll
                for (int j = 0; j < 4; j++) {
                    wmma::mma_sync(acc[ms][j], ah, bh[j], acc[ms][j]);
                    wmma::mma_sync(acc[ms][j], ah, bl[j], acc[ms][j]);
                    wmma::mma_sync(acc[ms][j], al, bh[j], acc[ms][j]);
                }
            }
        }
        __syncthreads();
        stage++; if (stage >= 3) stage = 0;
    }

    #pragma unroll
    for (int ms = 0; ms < 2; ms++)
        #pragma unroll
        for (int j = 0; j < 4; j++) {
            size_t off = (size_t)b * outB
                         + (size_t)(row0 + wm * 32 + ms * 16) * Cc
                         + (c0 + wn * 64 + j * 16);
            wmma::store_matrix_sync(Out + off, acc[ms][j], Cc, wmma::mem_row_major);
        }
}

// ---------------------------------------------------------------------------
// Mid (fp32): G[b,m,o] = (w_m/N) * sum_i R[m,i,o] * F[b,m,i]
// ---------------------------------------------------------------------------
__global__ __launch_bounds__(256) void mid_kernel(const float* __restrict__ R) {
    __shared__ float Are[16][34];
    __shared__ float Aim[16][34];
    __shared__ float Bs[16][64];

    const int m = blockIdx.y;
    const int o0 = blockIdx.x * 64;
    const int tid = threadIdx.x;
    const int tx = tid & 15, ty = tid >> 4;

    float ar[2][4] = {}, ai[2][4] = {};
    const float* Rm = R + (size_t)m * Cc * Cc;
    const int la_c = tid & 15, la_r0 = tid >> 4;
    const int lb_c = tid & 63, lb_r0 = tid >> 6;

    for (int k0 = 0; k0 < Cc; k0 += 16) {
        #pragma unroll
        for (int i = 0; i < 2; i++) {
            int r = la_r0 + i * 16;
            size_t g = (size_t)r * Mm * Cc + (size_t)m * Cc + (k0 + la_c);
            Are[la_c][r] = d_Fre[g];
            Aim[la_c][r] = d_Fim[g];
        }
        #pragma unroll
        for (int i = 0; i < 4; i++) {
            int r = lb_r0 + i * 4;
            Bs[r][lb_c] = Rm[(size_t)(k0 + r) * Cc + o0 + lb_c];
        }
        __syncthreads();
        #pragma unroll
        for (int k = 0; k < 16; k++) {
            float are0 = Are[k][ty * 2], are1 = Are[k][ty * 2 + 1];
            float aim0 = Aim[k][ty * 2], aim1 = Aim[k][ty * 2 + 1];
            float4 b4 = *(const float4*)&Bs[k][tx * 4];
            float bv[4] = {b4.x, b4.y, b4.z, b4.w};
            #pragma unroll
            for (int j = 0; j < 4; j++) {
                ar[0][j] += are0 * bv[j];
                ar[1][j] += are1 * bv[j];
                ai[0][j] += aim0 * bv[j];
                ai[1][j] += aim1 * bv[j];
            }
        }
        __syncthreads();
    }
    const float scale = (m == 0) ? (1.0f / Nn) : (2.0f / Nn);
    #pragma unroll
    for (int i = 0; i < 2; i++) {
        int bidx = ty * 2 + i;
        size_t base = (size_t)bidx * Mm * Cc + (size_t)m * Cc + o0 + tx * 4;
        float4 re = make_float4(scale * ar[i][0], scale * ar[i][1], scale * ar[i][2], scale * ar[i][3]);
        float4 im = make_float4(scale * ai[i][0], scale * ai[i][1], scale * ai[i][2], scale * ai[i][3]);
        *(float4*)&d_Gre[base] = re;
        *(float4*)&d_Gim[base] = im;
    }
}

// ---------------------------------------------------------------------------
// Combine: out[n] = v[n] + C[n] - S[n];  out[N-n] = v[N-n] + C[n] + S[n]
// grid (2048, 32), 64 threads (one float4 per thread)
// ---------------------------------------------------------------------------
__global__ __launch_bounds__(64) void combine(const float* __restrict__ v,
                                              float* __restrict__ out) {
    const int n = blockIdx.x, b = blockIdx.y;
    const int o = threadIdx.x * 4;
    size_t hidx = ((size_t)b * NH + n) * Cc + o;
    float4 c = *(const float4*)(d_C + hidx);
    float4 s = *(const float4*)(d_S + hidx);
    size_t i1 = ((size_t)b * Nn + n) * Cc + o;
    float4 v1 = *(const float4*)(v + i1);
    *(float4*)(out + i1) = make_float4(v1.x + c.x - s.x, v1.y + c.y - s.y,
                                       v1.z + c.z - s.z, v1.w + c.w - s.w);
    if (n > 0) {
        size_t i2 = ((size_t)b * Nn + (Nn - n)) * Cc + o;
        float4 v2 = *(const float4*)(v + i2);
        *(float4*)(out + i2) = make_float4(v2.x + c.x + s.x, v2.y + c.y + s.y,
                                           v2.z + c.z + s.z, v2.w + c.w + s.w);
    }
}

// out[b,2048,o] = v[b,2048,o] + sum_m (-1)^m * Gre'[b,m,o]
__global__ __launch_bounds__(64) void row2048(const float* __restrict__ v,
                                              float* __restrict__ out) {
    const int b = blockIdx.x;
    const int o = threadIdx.x * 4;
    float4 acc = make_float4(0.f, 0.f, 0.f, 0.f);
    #pragma unroll 4
    for (int m = 0; m < Mm; m += 2) {
        float4 g0 = *(const float4*)(d_Gre + ((size_t)b * Mm + m) * Cc + o);
        float4 g1 = *(const float4*)(d_Gre + ((size_t)b * Mm + m + 1) * Cc + o);
        acc.x += g0.x - g1.x; acc.y += g0.y - g1.y;
        acc.z += g0.z - g1.z; acc.w += g0.w - g1.w;
    }
    size_t idx = ((size_t)b * Nn + 2048) * Cc + o;
    float4 vv = *(const float4*)(v + idx);
    *(float4*)(out + idx) = make_float4(vv.x + acc.x, vv.y + acc.y,
                                        vv.z + acc.z, vv.w + acc.w);
}

// ---------------------------------------------------------------------------
extern "C" void kernel_launch(void* const* d_in, const int* in_sizes, int n_in,
                              void* d_out, int out_size) {
    const float* v = (const float*)d_in[0];
    const float* R = (const float*)d_in[1];
    float* out = (float*)d_out;

    const int smG = 3 * STAGE;  // 113664
    cudaFuncSetAttribute(gemm_ws, cudaFuncAttributeMaxDynamicSharedMemorySize, smG);

    genA_fwd<<<(Mm * KF) / 256, 256>>>();
    genA_inv<<<(NH * Mm) / 256, 256>>>();
    packVpVm<<<(int)(((size_t)Bb * KF * 64 + 255) / 256), 256>>>(v);
    gemm_ws<<<dim3(2, 8, Bb), 256, smG>>>(0);
    mid_kernel<<<dim3(Cc / 64, Mm), 256>>>(R);
    pack_G<<<(int)(((size_t)Bb * Mm * Cc / 4) / 256), 256>>>();
    gemm_ws<<<dim3(2, 32, Bb), 256, smG>>>(1);
    combine<<<dim3(NH, Bb), 64>>>(v, out);
    row2048<<<Bb, 64>>>(v, out);
}

// round 6
// speedup vs baseline: 2.4894x; 1.7847x over previous
#include <cuda_runtime.h>
#include <cuda_fp16.h>
#include <mma.h>
#include <cstdint>

using namespace nvcuda;

#define Bb 32
#define Nn 4096
#define Mm 512
#define Cc 256
#define KF 2080            // folded forward K (0..2048 data, padded to 65*32)
#define NH 2048            // half length for inverse rows

// ---------------------------------------------------------------------------
// Global scratch (static __device__ — no runtime allocation)
// ---------------------------------------------------------------------------
// Forward twiddles [512][KF]: cos hi/lo, (-sin) hi/lo  (fp16 2-term split)
__device__ __align__(16) __half g_AcosH[Mm * KF];
__device__ __align__(16) __half g_AcosL[Mm * KF];
__device__ __align__(16) __half g_AsinH[Mm * KF];
__device__ __align__(16) __half g_AsinL[Mm * KF];
// Folded v (single fp16 plane): vp = v[k]+v[N-k], vm = v[k]-v[N-k]; [b][KF][256]
__device__ __align__(16) __half g_Vp[(size_t)Bb * KF * Cc];
__device__ __align__(16) __half g_Vm[(size_t)Bb * KF * Cc];
// Inverse twiddles [2048 n][512 m]: cos hi/lo, sin hi/lo
__device__ __align__(16) __half g_icosH[NH * Mm];
__device__ __align__(16) __half g_icosL[NH * Mm];
__device__ __align__(16) __half g_isinH[NH * Mm];
__device__ __align__(16) __half g_isinL[NH * Mm];
// Scaled spectra (single fp16 plane): [b][512][256]
__device__ __align__(16) __half g_Gre16[(size_t)Bb * Mm * Cc];
__device__ __align__(16) __half g_Gim16[(size_t)Bb * Mm * Cc];
// fp32 intermediates
__device__ float d_Fre[Bb * Mm * Cc];
__device__ float d_Fim[Bb * Mm * Cc];
__device__ float d_Gre[Bb * Mm * Cc];
__device__ float d_Gim[Bb * Mm * Cc];
// Inverse half-spectrum results: [b][2048][256]
__device__ float d_C[(size_t)Bb * NH * Cc];
__device__ float d_S[(size_t)Bb * NH * Cc];

// ---------------------------------------------------------------------------
__device__ __forceinline__ uint32_t s2u(const void* p) {
    uint32_t a;
    asm("{ .reg .u64 t; cvta.to.shared.u64 t, %1; cvt.u32.u64 %0, t; }"
        : "=r"(a) : "l"(p));
    return a;
}

#define CP16(dst, src) \
    asm volatile("cp.async.cg.shared.global [%0], [%1], 16;" :: "r"(dst), "l"(src))
#define CP_COMMIT() asm volatile("cp.async.commit_group;")
#define CP_WAIT2()  asm volatile("cp.async.wait_group 2;" ::: "memory")
#define CP_WAIT1()  asm volatile("cp.async.wait_group 1;" ::: "memory")
#define CP_WAIT0()  asm volatile("cp.async.wait_group 0;" ::: "memory")

__device__ __forceinline__ void split_h(float x, __half& hi, __half& lo) {
    hi = __float2half(x);
    lo = __float2half(x - __half2float(hi));
}

typedef wmma::fragment<wmma::matrix_a, 16, 16, 16, __half, wmma::row_major> FragA;
typedef wmma::fragment<wmma::matrix_b, 16, 16, 16, __half, wmma::row_major> FragB;
typedef wmma::fragment<wmma::accumulator, 16, 16, 16, float> FragC;

// ---------------------------------------------------------------------------
// Prep kernels
// ---------------------------------------------------------------------------
__global__ __launch_bounds__(256) void genA_fwd() {
    int idx = blockIdx.x * blockDim.x + threadIdx.x;
    if (idx >= Mm * KF) return;
    int m = idx / KF, k = idx - m * KF;
    int t = (int)(((long long)m * k) & (Nn - 1));
    float s, c;
    sincospif((float)t * (1.0f / 2048.0f), &s, &c);
    __half h, l;
    split_h(c, h, l);
    g_AcosH[idx] = h; g_AcosL[idx] = l;
    split_h(-s, h, l);
    g_AsinH[idx] = h; g_AsinL[idx] = l;
}

__global__ __launch_bounds__(256) void genA_inv() {
    int idx = blockIdx.x * blockDim.x + threadIdx.x;
    if (idx >= NH * Mm) return;
    int n = idx >> 9, m = idx & 511;
    int t = (int)(((long long)m * n) & (Nn - 1));
    float s, c;
    sincospif((float)t * (1.0f / 2048.0f), &s, &c);
    __half h, l;
    split_h(c, h, l);
    g_icosH[idx] = h; g_icosL[idx] = l;
    split_h(s, h, l);
    g_isinH[idx] = h; g_isinL[idx] = l;
}

// Fold v -> vp/vm single fp16 plane.  idx4 over [b][KF][256/4]
__global__ __launch_bounds__(256) void packVpVm(const float* __restrict__ v) {
    size_t idx4 = (size_t)blockIdx.x * blockDim.x + threadIdx.x;
    if (idx4 >= (size_t)Bb * KF * 64) return;
    int b = (int)(idx4 / (KF * 64));
    int rem = (int)(idx4 - (size_t)b * (KF * 64));
    int k = rem >> 6, i = (rem & 63) * 4;
    float4 vp, vm;
    if (k == 0) {
        vp = *(const float4*)(v + ((size_t)b * Nn) * Cc + i);
        vm = make_float4(0.f, 0.f, 0.f, 0.f);
    } else if (k < 2048) {
        float4 a = *(const float4*)(v + ((size_t)b * Nn + k) * Cc + i);
        float4 c = *(const float4*)(v + ((size_t)b * Nn + (Nn - k)) * Cc + i);
        vp = make_float4(a.x + c.x, a.y + c.y, a.z + c.z, a.w + c.w);
        vm = make_float4(a.x - c.x, a.y - c.y, a.z - c.z, a.w - c.w);
    } else if (k == 2048) {
        vp = *(const float4*)(v + ((size_t)b * Nn + 2048) * Cc + i);
        vm = make_float4(0.f, 0.f, 0.f, 0.f);
    } else {
        vp = make_float4(0.f, 0.f, 0.f, 0.f);
        vm = vp;
    }
    size_t base = ((size_t)b * KF + k) * Cc + i;
    *(__half2*)(g_Vp + base)     = __half2{__float2half(vp.x), __float2half(vp.y)};
    *(__half2*)(g_Vp + base + 2) = __half2{__float2half(vp.z), __float2half(vp.w)};
    *(__half2*)(g_Vm + base)     = __half2{__float2half(vm.x), __float2half(vm.y)};
    *(__half2*)(g_Vm + base + 2) = __half2{__float2half(vm.z), __float2half(vm.w)};
}

// Convert scaled G -> single fp16 plane.
__global__ __launch_bounds__(256) void pack_G() {
    size_t idx4 = (size_t)blockIdx.x * blockDim.x + threadIdx.x;
    size_t base = idx4 * 4;
    if (base >= (size_t)Bb * Mm * Cc) return;
    float4 re = *(const float4*)(d_Gre + base);
    float4 im = *(const float4*)(d_Gim + base);
    *(__half2*)(g_Gre16 + base)     = __half2{__float2half(re.x), __float2half(re.y)};
    *(__half2*)(g_Gre16 + base + 2) = __half2{__float2half(re.z), __float2half(re.w)};
    *(__half2*)(g_Gim16 + base)     = __half2{__float2half(im.x), __float2half(im.y)};
    *(__half2*)(g_Gim16 + base + 2) = __half2{__float2half(im.z), __float2half(im.w)};
}

// ---------------------------------------------------------------------------
// Unified WMMA GEMM (fp16, A 2-term split, B single plane; 3-stage cp.async).
// CTA 128(rows) x 256(cols), 512 threads, 16 warps, warp tile 32x64.
// mode 0 (fwd): A [512][KF] twiddles, B [b][KF][256] vp/vm -> F [b][512][256]
// mode 1 (inv): A [2048][512],        B [b][512][256] G    -> C/S [b][2048][256]
// grid: (1, nyt*2, 32); comp = cos/re vs sin/im.
// Stage (37888B): Ah[128][40] @0, Al @10240, B[32][264] @20480 (16896B)
// ---------------------------------------------------------------------------
#define STAGE 37888

__global__ __launch_bounds__(512) void gemm_ws(int mode) {
    extern __shared__ __align__(16) char sm[];
    const uint32_t sb = s2u(sm);
    const int tid = threadIdx.x;
    const int warp = tid >> 5;
    const int wm = warp >> 2, wn = warp & 3;
    const int b = blockIdx.z;
    const int nyt = mode ? 16 : 4;
    const int y = blockIdx.y;
    const int comp = (y >= nyt) ? 1 : 0;
    const int yt = comp ? (y - nyt) : y;

    const __half *Ah, *Al, *Bp;
    float* Out;
    int Astride, K, NCH;
    size_t outB;
    if (mode == 0) {
        Astride = KF; K = KF; NCH = KF / 32; outB = (size_t)Mm * Cc;
        if (comp) { Ah = g_AsinH; Al = g_AsinL; Bp = g_Vm; Out = d_Fim; }
        else      { Ah = g_AcosH; Al = g_AcosL; Bp = g_Vp; Out = d_Fre; }
    } else {
        Astride = Mm; K = Mm; NCH = Mm / 32; outB = (size_t)NH * Cc;
        if (comp) { Ah = g_isinH; Al = g_isinL; Bp = g_Gim16; Out = d_S; }
        else      { Ah = g_icosH; Al = g_icosL; Bp = g_Gre16; Out = d_C; }
    }
    const int row0 = yt * 128;

    FragC acc[2][4];
    #pragma unroll
    for (int a = 0; a < 2; a++)
        #pragma unroll
        for (int j = 0; j < 4; j++) wmma::fill_fragment(acc[a][j], 0.0f);

    const int ar = tid >> 2, aq = tid & 3;   // A loader: 128 rows x 4 quads
    const int br = tid >> 4, bs = tid & 15;  // B loader: 32 rows x 16 segs

    auto load = [&](int stage, int k0) {
        uint32_t s0 = sb + stage * STAGE;
        size_t ga = (size_t)(row0 + ar) * Astride + k0 + aq * 8;
        uint32_t ad = s0 + ar * 80 + aq * 16;
        CP16(ad, Ah + ga);
        CP16(ad + 10240, Al + ga);
        size_t gb = ((size_t)b * K + k0 + br) * Cc + bs * 8;
        uint32_t bd = s0 + 20480 + br * 528 + bs * 16;
        CP16(bd, Bp + gb);
        CP16(bd + 256, Bp + gb + 128);
        CP_COMMIT();
    };

    load(0, 0);
    load(1, 32);

    int stage = 0;
    for (int c = 0; c < NCH; c++) {
        if (c + 2 < NCH) {
            int ns = stage + 2; if (ns >= 3) ns -= 3;
            load(ns, (c + 2) * 32);
            CP_WAIT2();
        } else if (c + 1 < NCH) {
            CP_WAIT1();
        } else {
            CP_WAIT0();
        }
        __syncthreads();

        const char* base = sm + stage * STAGE;
        const __half* Ahs = (const __half*)(base);
        const __half* Als = (const __half*)(base + 10240);
        const __half* Bs  = (const __half*)(base + 20480);

        #pragma unroll
        for (int ks = 0; ks < 2; ks++) {
            const int kk = ks * 16;
            FragB bf[4];
            #pragma unroll
            for (int j = 0; j < 4; j++)
                wmma::load_matrix_sync(bf[j], Bs + kk * 264 + wn * 64 + j * 16, 264);
            #pragma unroll
            for (int ms = 0; ms < 2; ms++) {
                const int ao = (wm * 32 + ms * 16) * 40 + kk;
                FragA ah, al;
                wmma::load_matrix_sync(ah, Ahs + ao, 40);
                wmma::load_matrix_sync(al, Als + ao, 40);
                #pragma unroll
                for (int j = 0; j < 4; j++) {
                    wmma::mma_sync(acc[ms][j], ah, bf[j], acc[ms][j]);
                    wmma::mma_sync(acc[ms][j], al, bf[j], acc[ms][j]);
                }
            }
        }
        __syncthreads();
        stage++; if (stage >= 3) stage = 0;
    }

    #pragma unroll
    for (int ms = 0; ms < 2; ms++)
        #pragma unroll
        for (int j = 0; j < 4; j++) {
            size_t off = (size_t)b * outB
                         + (size_t)(row0 + wm * 32 + ms * 16) * Cc
                         + (wn * 64 + j * 16);
            wmma::store_matrix_sync(Out + off, acc[ms][j], Cc, wmma::mem_row_major);
        }
}

// ---------------------------------------------------------------------------
// Mid (fp32): G[b,m,o] = (w_m/N) * sum_i R[m,i,o] * F[b,m,i]
// ---------------------------------------------------------------------------
__global__ __launch_bounds__(256) void mid_kernel(const float* __restrict__ R) {
    __shared__ float Are[16][34];
    __shared__ float Aim[16][34];
    __shared__ float Bs[16][64];

    const int m = blockIdx.y;
    const int o0 = blockIdx.x * 64;
    const int tid = threadIdx.x;
    const int tx = tid & 15, ty = tid >> 4;

    float ar[2][4] = {}, ai[2][4] = {};
    const float* Rm = R + (size_t)m * Cc * Cc;
    const int la_c = tid & 15, la_r0 = tid >> 4;
    const int lb_c = tid & 63, lb_r0 = tid >> 6;

    for (int k0 = 0; k0 < Cc; k0 += 16) {
        #pragma unroll
        for (int i = 0; i < 2; i++) {
            int r = la_r0 + i * 16;
            size_t g = (size_t)r * Mm * Cc + (size_t)m * Cc + (k0 + la_c);
            Are[la_c][r] = d_Fre[g];
            Aim[la_c][r] = d_Fim[g];
        }
        #pragma unroll
        for (int i = 0; i < 4; i++) {
            int r = lb_r0 + i * 4;
            Bs[r][lb_c] = Rm[(size_t)(k0 + r) * Cc + o0 + lb_c];
        }
        __syncthreads();
        #pragma unroll
        for (int k = 0; k < 16; k++) {
            float are0 = Are[k][ty * 2], are1 = Are[k][ty * 2 + 1];
            float aim0 = Aim[k][ty * 2], aim1 = Aim[k][ty * 2 + 1];
            float4 b4 = *(const float4*)&Bs[k][tx * 4];
            float bv[4] = {b4.x, b4.y, b4.z, b4.w};
            #pragma unroll
            for (int j = 0; j < 4; j++) {
                ar[0][j] += are0 * bv[j];
                ar[1][j] += are1 * bv[j];
                ai[0][j] += aim0 * bv[j];
                ai[1][j] += aim1 * bv[j];
            }
        }
        __syncthreads();
    }
    const float scale = (m == 0) ? (1.0f / Nn) : (2.0f / Nn);
    #pragma unroll
    for (int i = 0; i < 2; i++) {
        int bidx = ty * 2 + i;
        size_t base = (size_t)bidx * Mm * Cc + (size_t)m * Cc + o0 + tx * 4;
        float4 re = make_float4(scale * ar[i][0], scale * ar[i][1], scale * ar[i][2], scale * ar[i][3]);
        float4 im = make_float4(scale * ai[i][0], scale * ai[i][1], scale * ai[i][2], scale * ai[i][3]);
        *(float4*)&d_Gre[base] = re;
        *(float4*)&d_Gim[base] = im;
    }
}

// ---------------------------------------------------------------------------
// Combine: out[n] = v[n] + C[n] - S[n];  out[N-n] = v[N-n] + C[n] + S[n]
// ---------------------------------------------------------------------------
__global__ __launch_bounds__(64) void combine(const float* __restrict__ v,
                                              float* __restrict__ out) {
    const int n = blockIdx.x, b = blockIdx.y;
    const int o = threadIdx.x * 4;
    size_t hidx = ((size_t)b * NH + n) * Cc + o;
    float4 c = *(const float4*)(d_C + hidx);
    float4 s = *(const float4*)(d_S + hidx);
    size_t i1 = ((size_t)b * Nn + n) * Cc + o;
    float4 v1 = *(const float4*)(v + i1);
    *(float4*)(out + i1) = make_float4(v1.x + c.x - s.x, v1.y + c.y - s.y,
                                       v1.z + c.z - s.z, v1.w + c.w - s.w);
    if (n > 0) {
        size_t i2 = ((size_t)b * Nn + (Nn - n)) * Cc + o;
        float4 v2 = *(const float4*)(v + i2);
        *(float4*)(out + i2) = make_float4(v2.x + c.x + s.x, v2.y + c.y + s.y,
                                           v2.z + c.z + s.z, v2.w + c.w + s.w);
    }
}

// out[b,2048,o] = v[b,2048,o] + sum_m (-1)^m * Gre'[b,m,o]
__global__ __launch_bounds__(64) void row2048(const float* __restrict__ v,
                                              float* __restrict__ out) {
    const int b = blockIdx.x;
    const int o = threadIdx.x * 4;
    float4 acc = make_float4(0.f, 0.f, 0.f, 0.f);
    #pragma unroll 4
    for (int m = 0; m < Mm; m += 2) {
        float4 g0 = *(const float4*)(d_Gre + ((size_t)b * Mm + m) * Cc + o);
        float4 g1 = *(const float4*)(d_Gre + ((size_t)b * Mm + m + 1) * Cc + o);
        acc.x += g0.x - g1.x; acc.y += g0.y - g1.y;
        acc.z += g0.z - g1.z; acc.w += g0.w - g1.w;
    }
    size_t idx = ((size_t)b * Nn + 2048) * Cc + o;
    float4 vv = *(const float4*)(v + idx);
    *(float4*)(out + idx) = make_float4(vv.x + acc.x, vv.y + acc.y,
                                        vv.z + acc.z, vv.w + acc.w);
}

// ---------------------------------------------------------------------------
extern "C" void kernel_launch(void* const* d_in, const int* in_sizes, int n_in,
                              void* d_out, int out_size) {
    const float* v = (const float*)d_in[0];
    const float* R = (const float*)d_in[1];
    float* out = (float*)d_out;

    const int smG = 3 * STAGE;  // 113664
    cudaFuncSetAttribute(gemm_ws, cudaFuncAttributeMaxDynamicSharedMemorySize, smG);

    genA_fwd<<<(Mm * KF) / 256, 256>>>();
    genA_inv<<<(NH * Mm) / 256, 256>>>();
    packVpVm<<<(int)(((size_t)Bb * KF * 64 + 255) / 256), 256>>>(v);
    gemm_ws<<<dim3(1, 8, Bb), 512, smG>>>(0);
    mid_kernel<<<dim3(Cc / 64, Mm), 256>>>(R);
    pack_G<<<(int)(((size_t)Bb * Mm * Cc / 4) / 256), 256>>>();
    gemm_ws<<<dim3(1, 32, Bb), 512, smG>>>(1);
    combine<<<dim3(NH, Bb), 64>>>(v, out);
    row2048<<<Bb, 64>>>(v, out);
}

// round 7
// speedup vs baseline: 3.2960x; 1.3240x over previous
#include <cuda_runtime.h>
#include <cuda_fp16.h>
#include <mma.h>
#include <cstdint>

using namespace nvcuda;

#define Bb 32
#define Nn 4096
#define Mm 512
#define Cc 256
#define KF 2080            // folded forward K (0..2048 data, padded to 65*32)
#define NH 2048            // half length for inverse rows

// ---------------------------------------------------------------------------
// Global scratch (static __device__ — no runtime allocation)
// ---------------------------------------------------------------------------
// Forward twiddles [512][KF]: cos, -sin (single fp16 plane)
__device__ __align__(16) __half g_Acos[Mm * KF];
__device__ __align__(16) __half g_Asin[Mm * KF];
// Folded v: vp = v[k]+v[N-k], vm = v[k]-v[N-k]; [b][KF][256] fp16
__device__ __align__(16) __half g_Vp[(size_t)Bb * KF * Cc];
__device__ __align__(16) __half g_Vm[(size_t)Bb * KF * Cc];
// Inverse twiddles [2048 n][512 m]: cos, sin fp16
__device__ __align__(16) __half g_icos[NH * Mm];
__device__ __align__(16) __half g_isin[NH * Mm];
// Scaled spectra fp16: [b][512][256]
__device__ __align__(16) __half g_Gre16[(size_t)Bb * Mm * Cc];
__device__ __align__(16) __half g_Gim16[(size_t)Bb * Mm * Cc];
// fp32 intermediates
__device__ float d_Fre[Bb * Mm * Cc];
__device__ float d_Fim[Bb * Mm * Cc];
__device__ float d_Gre[Bb * Mm * Cc];     // fp32 Gre kept for row2048
// Inverse half-spectrum results: [b][2048][256]
__device__ float d_C[(size_t)Bb * NH * Cc];
__device__ float d_S[(size_t)Bb * NH * Cc];

// ---------------------------------------------------------------------------
__device__ __forceinline__ uint32_t s2u(const void* p) {
    uint32_t a;
    asm("{ .reg .u64 t; cvta.to.shared.u64 t, %1; cvt.u32.u64 %0, t; }"
        : "=r"(a) : "l"(p));
    return a;
}

#define CP16(dst, src) \
    asm volatile("cp.async.cg.shared.global [%0], [%1], 16;" :: "r"(dst), "l"(src))
#define CP_COMMIT() asm volatile("cp.async.commit_group;")
#define CP_WAIT3()  asm volatile("cp.async.wait_group 3;" ::: "memory")
#define CP_WAIT2()  asm volatile("cp.async.wait_group 2;" ::: "memory")
#define CP_WAIT1()  asm volatile("cp.async.wait_group 1;" ::: "memory")
#define CP_WAIT0()  asm volatile("cp.async.wait_group 0;" ::: "memory")

typedef wmma::fragment<wmma::matrix_a, 16, 16, 16, __half, wmma::row_major> FragA;
typedef wmma::fragment<wmma::matrix_b, 16, 16, 16, __half, wmma::row_major> FragB;
typedef wmma::fragment<wmma::accumulator, 16, 16, 16, float> FragC;

// ---------------------------------------------------------------------------
// Prep kernels
// ---------------------------------------------------------------------------
__global__ __launch_bounds__(256) void genA_fwd() {
    int idx = blockIdx.x * blockDim.x + threadIdx.x;
    if (idx >= Mm * KF) return;
    int m = idx / KF, k = idx - m * KF;
    int t = (int)(((long long)m * k) & (Nn - 1));
    float s, c;
    sincospif((float)t * (1.0f / 2048.0f), &s, &c);
    g_Acos[idx] = __float2half(c);
    g_Asin[idx] = __float2half(-s);
}

__global__ __launch_bounds__(256) void genA_inv() {
    int idx = blockIdx.x * blockDim.x + threadIdx.x;
    if (idx >= NH * Mm) return;
    int n = idx >> 9, m = idx & 511;
    int t = (int)(((long long)m * n) & (Nn - 1));
    float s, c;
    sincospif((float)t * (1.0f / 2048.0f), &s, &c);
    g_icos[idx] = __float2half(c);
    g_isin[idx] = __float2half(s);
}

// Fold v -> vp/vm fp16.  idx4 over [b][KF][256/4]
__global__ __launch_bounds__(256) void packVpVm(const float* __restrict__ v) {
    size_t idx4 = (size_t)blockIdx.x * blockDim.x + threadIdx.x;
    if (idx4 >= (size_t)Bb * KF * 64) return;
    int b = (int)(idx4 / (KF * 64));
    int rem = (int)(idx4 - (size_t)b * (KF * 64));
    int k = rem >> 6, i = (rem & 63) * 4;
    float4 vp, vm;
    if (k == 0) {
        vp = *(const float4*)(v + ((size_t)b * Nn) * Cc + i);
        vm = make_float4(0.f, 0.f, 0.f, 0.f);
    } else if (k < 2048) {
        float4 a = *(const float4*)(v + ((size_t)b * Nn + k) * Cc + i);
        float4 c = *(const float4*)(v + ((size_t)b * Nn + (Nn - k)) * Cc + i);
        vp = make_float4(a.x + c.x, a.y + c.y, a.z + c.z, a.w + c.w);
        vm = make_float4(a.x - c.x, a.y - c.y, a.z - c.z, a.w - c.w);
    } else if (k == 2048) {
        vp = *(const float4*)(v + ((size_t)b * Nn + 2048) * Cc + i);
        vm = make_float4(0.f, 0.f, 0.f, 0.f);
    } else {
        vp = make_float4(0.f, 0.f, 0.f, 0.f);
        vm = vp;
    }
    size_t base = ((size_t)b * KF + k) * Cc + i;
    *(__half2*)(g_Vp + base)     = __half2{__float2half(vp.x), __float2half(vp.y)};
    *(__half2*)(g_Vp + base + 2) = __half2{__float2half(vp.z), __float2half(vp.w)};
    *(__half2*)(g_Vm + base)     = __half2{__float2half(vm.x), __float2half(vm.y)};
    *(__half2*)(g_Vm + base + 2) = __half2{__float2half(vm.z), __float2half(vm.w)};
}

// ---------------------------------------------------------------------------
// Unified WMMA GEMM (single fp16 planes both operands; 4-stage cp.async).
// CTA 128(rows) x 256(cols), 512 threads, 16 warps, warp tile 32x64.
// mode 0 (fwd): A [512][KF] twiddles, B [b][KF][256] vp/vm -> F [b][512][256]
// mode 1 (inv): A [2048][512],        B [b][512][256] G    -> C/S [b][2048][256]
// grid: (1, nyt*2, 32); comp = cos/re vs sin/im.
// Stage (27136B): A[128][40] @0 (10240B), B[32][264] @10240 (16896B)
// ---------------------------------------------------------------------------
#define STAGE 27136

__global__ __launch_bounds__(512) void gemm_ws(int mode) {
    extern __shared__ __align__(16) char sm[];
    const uint32_t sb = s2u(sm);
    const int tid = threadIdx.x;
    const int warp = tid >> 5;
    const int wm = warp >> 2, wn = warp & 3;
    const int b = blockIdx.z;
    const int nyt = mode ? 16 : 4;
    const int y = blockIdx.y;
    const int comp = (y >= nyt) ? 1 : 0;
    const int yt = comp ? (y - nyt) : y;

    const __half *Ap, *Bp;
    float* Out;
    int Astride, K, NCH;
    size_t outB;
    if (mode == 0) {
        Astride = KF; K = KF; NCH = KF / 32; outB = (size_t)Mm * Cc;
        if (comp) { Ap = g_Asin; Bp = g_Vm; Out = d_Fim; }
        else      { Ap = g_Acos; Bp = g_Vp; Out = d_Fre; }
    } else {
        Astride = Mm; K = Mm; NCH = Mm / 32; outB = (size_t)NH * Cc;
        if (comp) { Ap = g_isin; Bp = g_Gim16; Out = d_S; }
        else      { Ap = g_icos; Bp = g_Gre16; Out = d_C; }
    }
    const int row0 = yt * 128;

    FragC acc[2][4];
    #pragma unroll
    for (int a = 0; a < 2; a++)
        #pragma unroll
        for (int j = 0; j < 4; j++) wmma::fill_fragment(acc[a][j], 0.0f);

    const int ar = tid >> 2, aq = tid & 3;   // A loader: 128 rows x 4 quads
    const int br = tid >> 4, bs = tid & 15;  // B loader: 32 rows x 16 segs

    auto load = [&](int stage, int k0) {
        uint32_t s0 = sb + stage * STAGE;
        size_t ga = (size_t)(row0 + ar) * Astride + k0 + aq * 8;
        CP16(s0 + ar * 80 + aq * 16, Ap + ga);
        size_t gb = ((size_t)b * K + k0 + br) * Cc + bs * 8;
        uint32_t bd = s0 + 10240 + br * 528 + bs * 16;
        CP16(bd, Bp + gb);
        CP16(bd + 256, Bp + gb + 128);
        CP_COMMIT();
    };

    load(0, 0);
    load(1, 32);
    load(2, 64);

    int stage = 0;
    for (int c = 0; c < NCH; c++) {
        if (c + 3 < NCH) {
            int ns = stage + 3; if (ns >= 4) ns -= 4;
            load(ns, (c + 3) * 32);
            CP_WAIT3();
        } else if (c + 2 < NCH) {
            CP_WAIT2();
        } else if (c + 1 < NCH) {
            CP_WAIT1();
        } else {
            CP_WAIT0();
        }
        __syncthreads();

        const char* base = sm + stage * STAGE;
        const __half* As = (const __half*)(base);
        const __half* Bs = (const __half*)(base + 10240);

        #pragma unroll
        for (int ks = 0; ks < 2; ks++) {
            const int kk = ks * 16;
            FragB bf[4];
            #pragma unroll
            for (int j = 0; j < 4; j++)
                wmma::load_matrix_sync(bf[j], Bs + kk * 264 + wn * 64 + j * 16, 264);
            #pragma unroll
            for (int ms = 0; ms < 2; ms++) {
                FragA af;
                wmma::load_matrix_sync(af, As + (wm * 32 + ms * 16) * 40 + kk, 40);
                #pragma unroll
                for (int j = 0; j < 4; j++)
                    wmma::mma_sync(acc[ms][j], af, bf[j], acc[ms][j]);
            }
        }
        __syncthreads();
        stage++; if (stage >= 4) stage = 0;
    }

    #pragma unroll
    for (int ms = 0; ms < 2; ms++)
        #pragma unroll
        for (int j = 0; j < 4; j++) {
            size_t off = (size_t)b * outB
                         + (size_t)(row0 + wm * 32 + ms * 16) * Cc
                         + (wn * 64 + j * 16);
            wmma::store_matrix_sync(Out + off, acc[ms][j], Cc, wmma::mem_row_major);
        }
}

// ---------------------------------------------------------------------------
// Mid (fp32): G[b,m,o] = (w_m/N) * sum_i R[m,i,o] * F[b,m,i]
// Epilogue writes fp16 planes for the inverse GEMM (pack_G fused) + fp32 Gre.
// ---------------------------------------------------------------------------
__global__ __launch_bounds__(256) void mid_kernel(const float* __restrict__ R) {
    __shared__ float Are[16][34];
    __shared__ float Aim[16][34];
    __shared__ float Bs[16][64];

    const int m = blockIdx.y;
    const int o0 = blockIdx.x * 64;
    const int tid = threadIdx.x;
    const int tx = tid & 15, ty = tid >> 4;

    float ar[2][4] = {}, ai[2][4] = {};
    const float* Rm = R + (size_t)m * Cc * Cc;
    const int la_c = tid & 15, la_r0 = tid >> 4;
    const int lb_c = tid & 63, lb_r0 = tid >> 6;

    for (int k0 = 0; k0 < Cc; k0 += 16) {
        #pragma unroll
        for (int i = 0; i < 2; i++) {
            int r = la_r0 + i * 16;
            size_t g = (size_t)r * Mm * Cc + (size_t)m * Cc + (k0 + la_c);
            Are[la_c][r] = d_Fre[g];
            Aim[la_c][r] = d_Fim[g];
        }
        #pragma unroll
        for (int i = 0; i < 4; i++) {
            int r = lb_r0 + i * 4;
            Bs[r][lb_c] = Rm[(size_t)(k0 + r) * Cc + o0 + lb_c];
        }
        __syncthreads();
        #pragma unroll
        for (int k = 0; k < 16; k++) {
            float are0 = Are[k][ty * 2], are1 = Are[k][ty * 2 + 1];
            float aim0 = Aim[k][ty * 2], aim1 = Aim[k][ty * 2 + 1];
            float4 b4 = *(const float4*)&Bs[k][tx * 4];
            float bv[4] = {b4.x, b4.y, b4.z, b4.w};
            #pragma unroll
            for (int j = 0; j < 4; j++) {
                ar[0][j] += are0 * bv[j];
                ar[1][j] += are1 * bv[j];
                ai[0][j] += aim0 * bv[j];
                ai[1][j] += aim1 * bv[j];
            }
        }
        __syncthreads();
    }
    const float scale = (m == 0) ? (1.0f / Nn) : (2.0f / Nn);
    #pragma unroll
    for (int i = 0; i < 2; i++) {
        int bidx = ty * 2 + i;
        size_t base = (size_t)bidx * Mm * Cc + (size_t)m * Cc + o0 + tx * 4;
        float r0 = scale * ar[i][0], r1 = scale * ar[i][1];
        float r2 = scale * ar[i][2], r3 = scale * ar[i][3];
        float i0_ = scale * ai[i][0], i1_ = scale * ai[i][1];
        float i2_ = scale * ai[i][2], i3_ = scale * ai[i][3];
        *(float4*)&d_Gre[base] = make_float4(r0, r1, r2, r3);
        *(__half2*)(g_Gre16 + base)     = __half2{__float2half(r0), __float2half(r1)};
        *(__half2*)(g_Gre16 + base + 2) = __half2{__float2half(r2), __float2half(r3)};
        *(__half2*)(g_Gim16 + base)     = __half2{__float2half(i0_), __float2half(i1_)};
        *(__half2*)(g_Gim16 + base + 2) = __half2{__float2half(i2_), __float2half(i3_)};
    }
}

// ---------------------------------------------------------------------------
// Combine: out[n] = v[n] + C[n] - S[n];  out[N-n] = v[N-n] + C[n] + S[n]
// ---------------------------------------------------------------------------
__global__ __launch_bounds__(64) void combine(const float* __restrict__ v,
                                              float* __restrict__ out) {
    const int n = blockIdx.x, b = blockIdx.y;
    const int o = threadIdx.x * 4;
    size_t hidx = ((size_t)b * NH + n) * Cc + o;
    float4 c = *(const float4*)(d_C + hidx);
    float4 s = *(const float4*)(d_S + hidx);
    size_t i1 = ((size_t)b * Nn + n) * Cc + o;
    float4 v1 = *(const float4*)(v + i1);
    *(float4*)(out + i1) = make_float4(v1.x + c.x - s.x, v1.y + c.y - s.y,
                                       v1.z + c.z - s.z, v1.w + c.w - s.w);
    if (n > 0) {
        size_t i2 = ((size_t)b * Nn + (Nn - n)) * Cc + o;
        float4 v2 = *(const float4*)(v + i2);
        *(float4*)(out + i2) = make_float4(v2.x + c.x + s.x, v2.y + c.y + s.y,
                                           v2.z + c.z + s.z, v2.w + c.w + s.w);
    }
}

// out[b,2048,o] = v[b,2048,o] + sum_m (-1)^m * Gre'[b,m,o]
__global__ __launch_bounds__(64) void row2048(const float* __restrict__ v,
                                              float* __restrict__ out) {
    const int b = blockIdx.x;
    const int o = threadIdx.x * 4;
    float4 acc = make_float4(0.f, 0.f, 0.f, 0.f);
    #pragma unroll 4
    for (int m = 0; m < Mm; m += 2) {
        float4 g0 = *(const float4*)(d_Gre + ((size_t)b * Mm + m) * Cc + o);
        float4 g1 = *(const float4*)(d_Gre + ((size_t)b * Mm + m + 1) * Cc + o);
        acc.x += g0.x - g1.x; acc.y += g0.y - g1.y;
        acc.z += g0.z - g1.z; acc.w += g0.w - g1.w;
    }
    size_t idx = ((size_t)b * Nn + 2048) * Cc + o;
    float4 vv = *(const float4*)(v + idx);
    *(float4*)(out + idx) = make_float4(vv.x + acc.x, vv.y + acc.y,
                                        vv.z + acc.z, vv.w + acc.w);
}

// ---------------------------------------------------------------------------
extern "C" void kernel_launch(void* const* d_in, const int* in_sizes, int n_in,
                              void* d_out, int out_size) {
    const float* v = (const float*)d_in[0];
    const float* R = (const float*)d_in[1];
    float* out = (float*)d_out;

    const int smG = 4 * STAGE;  // 108544
    cudaFuncSetAttribute(gemm_ws, cudaFuncAttributeMaxDynamicSharedMemorySize, smG);

    genA_fwd<<<(Mm * KF) / 256, 256>>>();
    genA_inv<<<(NH * Mm) / 256, 256>>>();
    packVpVm<<<(int)(((size_t)Bb * KF * 64 + 255) / 256), 256>>>(v);
    gemm_ws<<<dim3(1, 8, Bb), 512, smG>>>(0);
    mid_kernel<<<dim3(Cc / 64, Mm), 256>>>(R);
    gemm_ws<<<dim3(1, 32, Bb), 512, smG>>>(1);
    combine<<<dim3(NH, Bb), 64>>>(v, out);
    row2048<<<Bb, 64>>>(v, out);
}

// round 8
// speedup vs baseline: 3.7778x; 1.1462x over previous
#include <cuda_runtime.h>
#include <cuda_fp16.h>
#include <mma.h>
#include <cstdint>

using namespace nvcuda;

#define Bb 32
#define Nn 4096
#define Mm 512
#define Cc 256
#define KF 2080            // folded forward K (0..2048 data, padded to 65*32)
#define NH 2048            // half length for inverse rows

// ---------------------------------------------------------------------------
// Global scratch (static __device__ — no runtime allocation)
// ---------------------------------------------------------------------------
// Forward twiddles [512][KF]: cos, -sin fp16
__device__ __align__(16) __half g_Acos[Mm * KF];
__device__ __align__(16) __half g_Asin[Mm * KF];
// Folded v: vp = v[k]+v[N-k], vm = v[k]-v[N-k]; [b][KF][256] fp16
__device__ __align__(16) __half g_Vp[(size_t)Bb * KF * Cc];
__device__ __align__(16) __half g_Vm[(size_t)Bb * KF * Cc];
// Inverse twiddles [2048 n][512 m]: cos, sin fp16
__device__ __align__(16) __half g_icos[NH * Mm];
__device__ __align__(16) __half g_isin[NH * Mm];
// Scaled R in fp16 (w_m/N folded): [512 m][256 i][256 o]
__device__ __align__(16) __half g_R16[(size_t)Mm * Cc * Cc];
// Scaled spectra fp16: [b][512][256]
__device__ __align__(16) __half g_Gre16[(size_t)Bb * Mm * Cc];
__device__ __align__(16) __half g_Gim16[(size_t)Bb * Mm * Cc];
// fp32 intermediates
__device__ float d_Fre[Bb * Mm * Cc];
__device__ float d_Fim[Bb * Mm * Cc];
// Inverse half-spectrum results: [b][2048][256]
__device__ float d_C[(size_t)Bb * NH * Cc];
__device__ float d_S[(size_t)Bb * NH * Cc];

// ---------------------------------------------------------------------------
__device__ __forceinline__ uint32_t s2u(const void* p) {
    uint32_t a;
    asm("{ .reg .u64 t; cvta.to.shared.u64 t, %1; cvt.u32.u64 %0, t; }"
        : "=r"(a) : "l"(p));
    return a;
}

#define CP16(dst, src) \
    asm volatile("cp.async.cg.shared.global [%0], [%1], 16;" :: "r"(dst), "l"(src))
#define CP_COMMIT() asm volatile("cp.async.commit_group;")
#define CP_WAIT3()  asm volatile("cp.async.wait_group 3;" ::: "memory")
#define CP_WAIT2()  asm volatile("cp.async.wait_group 2;" ::: "memory")
#define CP_WAIT1()  asm volatile("cp.async.wait_group 1;" ::: "memory")
#define CP_WAIT0()  asm volatile("cp.async.wait_group 0;" ::: "memory")

typedef wmma::fragment<wmma::matrix_a, 16, 16, 16, __half, wmma::row_major> FragA;
typedef wmma::fragment<wmma::matrix_b, 16, 16, 16, __half, wmma::row_major> FragB;
typedef wmma::fragment<wmma::accumulator, 16, 16, 16, float> FragC;

// ---------------------------------------------------------------------------
// Prep kernels
// ---------------------------------------------------------------------------
__global__ __launch_bounds__(256) void genA_fwd() {
    int idx = blockIdx.x * blockDim.x + threadIdx.x;
    if (idx >= Mm * KF) return;
    int m = idx / KF, k = idx - m * KF;
    int t = (int)(((long long)m * k) & (Nn - 1));
    float s, c;
    sincospif((float)t * (1.0f / 2048.0f), &s, &c);
    g_Acos[idx] = __float2half(c);
    g_Asin[idx] = __float2half(-s);
}

__global__ __launch_bounds__(256) void genA_inv() {
    int idx = blockIdx.x * blockDim.x + threadIdx.x;
    if (idx >= NH * Mm) return;
    int n = idx >> 9, m = idx & 511;
    int t = (int)(((long long)m * n) & (Nn - 1));
    float s, c;
    sincospif((float)t * (1.0f / 2048.0f), &s, &c);
    g_icos[idx] = __float2half(c);
    g_isin[idx] = __float2half(s);
}

// R fp32 -> fp16 with w_m/N folded.
__global__ __launch_bounds__(256) void pack_R(const float* __restrict__ R) {
    size_t idx4 = (size_t)blockIdx.x * blockDim.x + threadIdx.x;
    size_t base = idx4 * 4;
    if (base >= (size_t)Mm * Cc * Cc) return;
    int m = (int)(base >> 16);
    float sc = (m == 0) ? (1.0f / Nn) : (2.0f / Nn);
    float4 x = *(const float4*)(R + base);
    *(__half2*)(g_R16 + base)     = __half2{__float2half(x.x * sc), __float2half(x.y * sc)};
    *(__half2*)(g_R16 + base + 2) = __half2{__float2half(x.z * sc), __float2half(x.w * sc)};
}

// Fold v -> vp/vm fp16.  idx4 over [b][KF][256/4]
__global__ __launch_bounds__(256) void packVpVm(const float* __restrict__ v) {
    size_t idx4 = (size_t)blockIdx.x * blockDim.x + threadIdx.x;
    if (idx4 >= (size_t)Bb * KF * 64) return;
    int b = (int)(idx4 / (KF * 64));
    int rem = (int)(idx4 - (size_t)b * (KF * 64));
    int k = rem >> 6, i = (rem & 63) * 4;
    float4 vp, vm;
    if (k == 0) {
        vp = *(const float4*)(v + ((size_t)b * Nn) * Cc + i);
        vm = make_float4(0.f, 0.f, 0.f, 0.f);
    } else if (k < 2048) {
        float4 a = *(const float4*)(v + ((size_t)b * Nn + k) * Cc + i);
        float4 c = *(const float4*)(v + ((size_t)b * Nn + (Nn - k)) * Cc + i);
        vp = make_float4(a.x + c.x, a.y + c.y, a.z + c.z, a.w + c.w);
        vm = make_float4(a.x - c.x, a.y - c.y, a.z - c.z, a.w - c.w);
    } else if (k == 2048) {
        vp = *(const float4*)(v + ((size_t)b * Nn + 2048) * Cc + i);
        vm = make_float4(0.f, 0.f, 0.f, 0.f);
    } else {
        vp = make_float4(0.f, 0.f, 0.f, 0.f);
        vm = vp;
    }
    size_t base = ((size_t)b * KF + k) * Cc + i;
    *(__half2*)(g_Vp + base)     = __half2{__float2half(vp.x), __float2half(vp.y)};
    *(__half2*)(g_Vp + base + 2) = __half2{__float2half(vp.z), __float2half(vp.w)};
    *(__half2*)(g_Vm + base)     = __half2{__float2half(vm.x), __float2half(vm.y)};
    *(__half2*)(g_Vm + base + 2) = __half2{__float2half(vm.z), __float2half(vm.w)};
}

// ---------------------------------------------------------------------------
// Unified WMMA GEMM (single fp16 planes; 4-stage cp.async) — unchanged.
// CTA 128(rows) x 256(cols), 512 threads, 16 warps, warp tile 32x64.
// Stage (27136B): A[128][40] @0 (10240B), B[32][264] @10240 (16896B)
// ---------------------------------------------------------------------------
#define STAGE 27136

__global__ __launch_bounds__(512) void gemm_ws(int mode) {
    extern __shared__ __align__(16) char sm[];
    const uint32_t sb = s2u(sm);
    const int tid = threadIdx.x;
    const int warp = tid >> 5;
    const int wm = warp >> 2, wn = warp & 3;
    const int b = blockIdx.z;
    const int nyt = mode ? 16 : 4;
    const int y = blockIdx.y;
    const int comp = (y >= nyt) ? 1 : 0;
    const int yt = comp ? (y - nyt) : y;

    const __half *Ap, *Bp;
    float* Out;
    int Astride, K, NCH;
    size_t outB;
    if (mode == 0) {
        Astride = KF; K = KF; NCH = KF / 32; outB = (size_t)Mm * Cc;
        if (comp) { Ap = g_Asin; Bp = g_Vm; Out = d_Fim; }
        else      { Ap = g_Acos; Bp = g_Vp; Out = d_Fre; }
    } else {
        Astride = Mm; K = Mm; NCH = Mm / 32; outB = (size_t)NH * Cc;
        if (comp) { Ap = g_isin; Bp = g_Gim16; Out = d_S; }
        else      { Ap = g_icos; Bp = g_Gre16; Out = d_C; }
    }
    const int row0 = yt * 128;

    FragC acc[2][4];
    #pragma unroll
    for (int a = 0; a < 2; a++)
        #pragma unroll
        for (int j = 0; j < 4; j++) wmma::fill_fragment(acc[a][j], 0.0f);

    const int ar = tid >> 2, aq = tid & 3;
    const int br = tid >> 4, bs = tid & 15;

    auto load = [&](int stage, int k0) {
        uint32_t s0 = sb + stage * STAGE;
        size_t ga = (size_t)(row0 + ar) * Astride + k0 + aq * 8;
        CP16(s0 + ar * 80 + aq * 16, Ap + ga);
        size_t gb = ((size_t)b * K + k0 + br) * Cc + bs * 8;
        uint32_t bd = s0 + 10240 + br * 528 + bs * 16;
        CP16(bd, Bp + gb);
        CP16(bd + 256, Bp + gb + 128);
        CP_COMMIT();
    };

    load(0, 0);
    load(1, 32);
    load(2, 64);

    int stage = 0;
    for (int c = 0; c < NCH; c++) {
        if (c + 3 < NCH) {
            int ns = stage + 3; if (ns >= 4) ns -= 4;
            load(ns, (c + 3) * 32);
            CP_WAIT3();
        } else if (c + 2 < NCH) {
            CP_WAIT2();
        } else if (c + 1 < NCH) {
            CP_WAIT1();
        } else {
            CP_WAIT0();
        }
        __syncthreads();

        const char* base = sm + stage * STAGE;
        const __half* As = (const __half*)(base);
        const __half* Bs = (const __half*)(base + 10240);

        #pragma unroll
        for (int ks = 0; ks < 2; ks++) {
            const int kk = ks * 16;
            FragB bf[4];
            #pragma unroll
            for (int j = 0; j < 4; j++)
                wmma::load_matrix_sync(bf[j], Bs + kk * 264 + wn * 64 + j * 16, 264);
            #pragma unroll
            for (int ms = 0; ms < 2; ms++) {
                FragA af;
                wmma::load_matrix_sync(af, As + (wm * 32 + ms * 16) * 40 + kk, 40);
                #pragma unroll
                for (int j = 0; j < 4; j++)
                    wmma::mma_sync(acc[ms][j], af, bf[j], acc[ms][j]);
            }
        }
        __syncthreads();
        stage++; if (stage >= 4) stage = 0;
    }

    #pragma unroll
    for (int ms = 0; ms < 2; ms++)
        #pragma unroll
        for (int j = 0; j < 4; j++) {
            size_t off = (size_t)b * outB
                         + (size_t)(row0 + wm * 32 + ms * 16) * Cc
                         + (wn * 64 + j * 16);
            wmma::store_matrix_sync(Out + off, acc[ms][j], Cc, wmma::mem_row_major);
        }
}

// ---------------------------------------------------------------------------
// Mid WMMA: for each mode m, G[32b, 256o] = F[32b, 256i] @ R16[m] (re & im).
// 256 threads, 8 warps; warp tile 32(b) x 32(o). K=256, B pipelined 4x32.
// smem: A_re[32][264] @0 (16896), A_im @16896, B stages @33792 (+s*16896)
// Epilogue bounce reuses B region: per warp 32x40 fp32 x2 comps (10240B).
// ---------------------------------------------------------------------------
#define MAST 16896
#define MBOFF 33792

__global__ __launch_bounds__(256) void mid_wmma() {
    extern __shared__ __align__(16) char sm[];
    const uint32_t sb = s2u(sm);
    const int tid = threadIdx.x;
    const int warp = tid >> 5, lane = tid & 31;
    const int m = blockIdx.x;

    __half* Are = (__half*)sm;
    __half* Aim = (__half*)(sm + MAST);

    // Load F[b=0..31][m][i=0..255] fp32, convert to fp16 in smem.
    #pragma unroll
    for (int it = 0; it < 8; it++) {
        int idx4 = tid + 256 * it;              // 2048 float4 per comp
        int row = idx4 >> 6, c4 = idx4 & 63;
        size_t g = ((size_t)row * Mm + m) * Cc + c4 * 4;
        float4 fr = *(const float4*)(d_Fre + g);
        float4 fi = *(const float4*)(d_Fim + g);
        int o = row * 264 + c4 * 4;
        *(__half2*)(Are + o)     = __half2{__float2half(fr.x), __float2half(fr.y)};
        *(__half2*)(Are + o + 2) = __half2{__float2half(fr.z), __float2half(fr.w)};
        *(__half2*)(Aim + o)     = __half2{__float2half(fi.x), __float2half(fi.y)};
        *(__half2*)(Aim + o + 2) = __half2{__float2half(fi.z), __float2half(fi.w)};
    }

    const int kr = tid >> 3, seg = tid & 7;     // B loader: 32 rows x 8 segs(64B)
    auto loadB = [&](int stage, int c) {
        uint32_t s0 = sb + MBOFF + stage * MAST;
        size_t gb = ((size_t)m * Cc + c * 32 + kr) * Cc + seg * 32;
        uint32_t bd = s0 + kr * 528 + seg * 64;
        CP16(bd,      g_R16 + gb);
        CP16(bd + 16, g_R16 + gb + 8);
        CP16(bd + 32, g_R16 + gb + 16);
        CP16(bd + 48, g_R16 + gb + 24);
        CP_COMMIT();
    };

    loadB(0, 0);
    loadB(1, 1);
    loadB(2, 2);
    __syncthreads();   // A ready (and stage-0 ordering via waits below)

    FragC accR[2][2], accI[2][2];
    #pragma unroll
    for (int a = 0; a < 2; a++)
        #pragma unroll
        for (int j = 0; j < 2; j++) {
            wmma::fill_fragment(accR[a][j], 0.0f);
            wmma::fill_fragment(accI[a][j], 0.0f);
        }

    int stage = 0;
    for (int c = 0; c < 8; c++) {
        if (c + 3 < 8) {
            int ns = stage + 3; if (ns >= 4) ns -= 4;
            loadB(ns, c + 3);
            CP_WAIT3();
        } else if (c + 2 < 8) {
            CP_WAIT2();
        } else if (c + 1 < 8) {
            CP_WAIT1();
        } else {
            CP_WAIT0();
        }
        __syncthreads();

        const __half* Bs = (const __half*)(sm + MBOFF + stage * MAST);
        #pragma unroll
        for (int ks = 0; ks < 2; ks++) {
            const int kk = c * 32 + ks * 16;
            FragB bf[2];
            #pragma unroll
            for (int j = 0; j < 2; j++)
                wmma::load_matrix_sync(bf[j], Bs + (ks * 16) * 264 + warp * 32 + j * 16, 264);
            #pragma unroll
            for (int ms = 0; ms < 2; ms++) {
                FragA ar_, ai_;
                wmma::load_matrix_sync(ar_, Are + ms * 16 * 264 + kk, 264);
                wmma::load_matrix_sync(ai_, Aim + ms * 16 * 264 + kk, 264);
                #pragma unroll
                for (int j = 0; j < 2; j++) {
                    wmma::mma_sync(accR[ms][j], ar_, bf[j], accR[ms][j]);
                    wmma::mma_sync(accI[ms][j], ai_, bf[j], accI[ms][j]);
                }
            }
        }
        __syncthreads();
        stage++; if (stage >= 4) stage = 0;
    }

    // Epilogue: bounce (stride 40 fp32) -> fp16 planes, coalesced row writes.
    float* bre = (float*)(sm + MBOFF) + warp * 2560;   // 32x40 = 1280 floats/comp
    float* bim = bre + 1280;
    #pragma unroll
    for (int ms = 0; ms < 2; ms++)
        #pragma unroll
        for (int j = 0; j < 2; j++) {
            wmma::store_matrix_sync(bre + ms * 16 * 40 + j * 16, accR[ms][j], 40, wmma::mem_row_major);
            wmma::store_matrix_sync(bim + ms * 16 * 40 + j * 16, accI[ms][j], 40, wmma::mem_row_major);
        }
    __syncwarp();
    #pragma unroll 4
    for (int r = 0; r < 32; r++) {
        size_t g = ((size_t)r * Mm + m) * Cc + warp * 32 + lane;
        g_Gre16[g] = __float2half(bre[r * 40 + lane]);
        g_Gim16[g] = __float2half(bim[r * 40 + lane]);
    }
}

// ---------------------------------------------------------------------------
// Combine: out[n] = v[n] + C[n] - S[n];  out[N-n] = v[N-n] + C[n] + S[n]
// ---------------------------------------------------------------------------
__global__ __launch_bounds__(64) void combine(const float* __restrict__ v,
                                              float* __restrict__ out) {
    const int n = blockIdx.x, b = blockIdx.y;
    const int o = threadIdx.x * 4;
    size_t hidx = ((size_t)b * NH + n) * Cc + o;
    float4 c = *(const float4*)(d_C + hidx);
    float4 s = *(const float4*)(d_S + hidx);
    size_t i1 = ((size_t)b * Nn + n) * Cc + o;
    float4 v1 = *(const float4*)(v + i1);
    *(float4*)(out + i1) = make_float4(v1.x + c.x - s.x, v1.y + c.y - s.y,
                                       v1.z + c.z - s.z, v1.w + c.w - s.w);
    if (n > 0) {
        size_t i2 = ((size_t)b * Nn + (Nn - n)) * Cc + o;
        float4 v2 = *(const float4*)(v + i2);
        *(float4*)(out + i2) = make_float4(v2.x + c.x + s.x, v2.y + c.y + s.y,
                                           v2.z + c.z + s.z, v2.w + c.w + s.w);
    }
}

// out[b,2048,o] = v[b,2048,o] + sum_m (-1)^m * Gre'[b,m,o]   (reads fp16 Gre)
__global__ __launch_bounds__(64) void row2048(const float* __restrict__ v,
                                              float* __restrict__ out) {
    const int b = blockIdx.x;
    const int o = threadIdx.x * 4;
    float acc0 = 0.f, acc1 = 0.f, acc2 = 0.f, acc3 = 0.f;
    #pragma unroll 8
    for (int m = 0; m < Mm; m++) {
        float sgn = (m & 1) ? -1.0f : 1.0f;
        const __half* g = g_Gre16 + ((size_t)b * Mm + m) * Cc + o;
        __half2 a = *(const __half2*)(g);
        __half2 bb = *(const __half2*)(g + 2);
        acc0 += sgn * __half2float(a.x);
        acc1 += sgn * __half2float(a.y);
        acc2 += sgn * __half2float(bb.x);
        acc3 += sgn * __half2float(bb.y);
    }
    size_t idx = ((size_t)b * Nn + 2048) * Cc + o;
    float4 vv = *(const float4*)(v + idx);
    *(float4*)(out + idx) = make_float4(vv.x + acc0, vv.y + acc1,
                                        vv.z + acc2, vv.w + acc3);
}

// ---------------------------------------------------------------------------
extern "C" void kernel_launch(void* const* d_in, const int* in_sizes, int n_in,
                              void* d_out, int out_size) {
    const float* v = (const float*)d_in[0];
    const float* R = (const float*)d_in[1];
    float* out = (float*)d_out;

    const int smG = 4 * STAGE;              // 108544
    const int smM = MBOFF + 4 * MAST;       // 101376 (>= bounce: 33792+81920=115712)
    const int smMid = 115712;
    cudaFuncSetAttribute(gemm_ws, cudaFuncAttributeMaxDynamicSharedMemorySize, smG);
    cudaFuncSetAttribute(mid_wmma, cudaFuncAttributeMaxDynamicSharedMemorySize, smMid);

    pack_R<<<(int)(((size_t)Mm * Cc * Cc / 4 + 255) / 256), 256>>>(R);
    genA_fwd<<<(Mm * KF) / 256, 256>>>();
    genA_inv<<<(NH * Mm) / 256, 256>>>();
    packVpVm<<<(int)(((size_t)Bb * KF * 64 + 255) / 256), 256>>>(v);
    gemm_ws<<<dim3(1, 8, Bb), 512, smG>>>(0);
    mid_wmma<<<Mm, 256, smMid>>>();
    gemm_ws<<<dim3(1, 32, Bb), 512, smG>>>(1);
    combine<<<dim3(NH, Bb), 64>>>(v, out);
    row2048<<<Bb, 64>>>(v, out);
}

// round 9
// speedup vs baseline: 3.8801x; 1.0271x over previous
#include <cuda_runtime.h>
#include <cuda_fp16.h>
#include <mma.h>
#include <cstdint>

using namespace nvcuda;

#define Bb 32
#define Nn 4096
#define Mm 512
#define Cc 256
#define KF 2080            // folded forward K (0..2048 data, padded to 65*32)
#define NH 2048            // half length for inverse rows

// ---------------------------------------------------------------------------
// Global scratch (static __device__ — no runtime allocation)
// ---------------------------------------------------------------------------
// Forward twiddles [512][KF]: cos, -sin fp16
__device__ __align__(16) __half g_Acos[Mm * KF];
__device__ __align__(16) __half g_Asin[Mm * KF];
// Folded v: vp = v[k]+v[N-k], vm = v[k]-v[N-k]; [b][KF][256] fp16
__device__ __align__(16) __half g_Vp[(size_t)Bb * KF * Cc];
__device__ __align__(16) __half g_Vm[(size_t)Bb * KF * Cc];
// Inverse twiddles [2048 n][512 m]: cos, sin fp16
__device__ __align__(16) __half g_icos[NH * Mm];
__device__ __align__(16) __half g_isin[NH * Mm];
// Scaled R in fp16 (w_m/N folded): [512 m][256 i][256 o]
__device__ __align__(16) __half g_R16[(size_t)Mm * Cc * Cc];
// Forward spectra fp16: [b][512][256]
__device__ __align__(16) __half g_Fre16[(size_t)Bb * Mm * Cc];
__device__ __align__(16) __half g_Fim16[(size_t)Bb * Mm * Cc];
// Scaled transformed spectra fp16: [b][512][256]
__device__ __align__(16) __half g_Gre16[(size_t)Bb * Mm * Cc];
__device__ __align__(16) __half g_Gim16[(size_t)Bb * Mm * Cc];

// ---------------------------------------------------------------------------
__device__ __forceinline__ uint32_t s2u(const void* p) {
    uint32_t a;
    asm("{ .reg .u64 t; cvta.to.shared.u64 t, %1; cvt.u32.u64 %0, t; }"
        : "=r"(a) : "l"(p));
    return a;
}

#define CP16(dst, src) \
    asm volatile("cp.async.cg.shared.global [%0], [%1], 16;" :: "r"(dst), "l"(src))
#define CP_COMMIT() asm volatile("cp.async.commit_group;")
#define CP_WAIT3()  asm volatile("cp.async.wait_group 3;" ::: "memory")
#define CP_WAIT2()  asm volatile("cp.async.wait_group 2;" ::: "memory")
#define CP_WAIT1()  asm volatile("cp.async.wait_group 1;" ::: "memory")
#define CP_WAIT0()  asm volatile("cp.async.wait_group 0;" ::: "memory")

typedef wmma::fragment<wmma::matrix_a, 16, 16, 16, __half, wmma::row_major> FragA;
typedef wmma::fragment<wmma::matrix_b, 16, 16, 16, __half, wmma::row_major> FragB;
typedef wmma::fragment<wmma::accumulator, 16, 16, 16, float> FragC;

// ---------------------------------------------------------------------------
// Prep kernels
// ---------------------------------------------------------------------------
__global__ __launch_bounds__(256) void genA_fwd() {
    int idx = blockIdx.x * blockDim.x + threadIdx.x;
    if (idx >= Mm * KF) return;
    int m = idx / KF, k = idx - m * KF;
    int t = (int)(((long long)m * k) & (Nn - 1));
    float s, c;
    sincospif((float)t * (1.0f / 2048.0f), &s, &c);
    g_Acos[idx] = __float2half(c);
    g_Asin[idx] = __float2half(-s);
}

__global__ __launch_bounds__(256) void genA_inv() {
    int idx = blockIdx.x * blockDim.x + threadIdx.x;
    if (idx >= NH * Mm) return;
    int n = idx >> 9, m = idx & 511;
    int t = (int)(((long long)m * n) & (Nn - 1));
    float s, c;
    sincospif((float)t * (1.0f / 2048.0f), &s, &c);
    g_icos[idx] = __float2half(c);
    g_isin[idx] = __float2half(s);
}

// R fp32 -> fp16 with w_m/N folded.
__global__ __launch_bounds__(256) void pack_R(const float* __restrict__ R) {
    size_t idx4 = (size_t)blockIdx.x * blockDim.x + threadIdx.x;
    size_t base = idx4 * 4;
    if (base >= (size_t)Mm * Cc * Cc) return;
    int m = (int)(base >> 16);
    float sc = (m == 0) ? (1.0f / Nn) : (2.0f / Nn);
    float4 x = *(const float4*)(R + base);
    *(__half2*)(g_R16 + base)     = __half2{__float2half(x.x * sc), __float2half(x.y * sc)};
    *(__half2*)(g_R16 + base + 2) = __half2{__float2half(x.z * sc), __float2half(x.w * sc)};
}

// Fold v -> vp/vm fp16.  idx4 over [b][KF][256/4]
__global__ __launch_bounds__(256) void packVpVm(const float* __restrict__ v) {
    size_t idx4 = (size_t)blockIdx.x * blockDim.x + threadIdx.x;
    if (idx4 >= (size_t)Bb * KF * 64) return;
    int b = (int)(idx4 / (KF * 64));
    int rem = (int)(idx4 - (size_t)b * (KF * 64));
    int k = rem >> 6, i = (rem & 63) * 4;
    float4 vp, vm;
    if (k == 0) {
        vp = *(const float4*)(v + ((size_t)b * Nn) * Cc + i);
        vm = make_float4(0.f, 0.f, 0.f, 0.f);
    } else if (k < 2048) {
        float4 a = *(const float4*)(v + ((size_t)b * Nn + k) * Cc + i);
        float4 c = *(const float4*)(v + ((size_t)b * Nn + (Nn - k)) * Cc + i);
        vp = make_float4(a.x + c.x, a.y + c.y, a.z + c.z, a.w + c.w);
        vm = make_float4(a.x - c.x, a.y - c.y, a.z - c.z, a.w - c.w);
    } else if (k == 2048) {
        vp = *(const float4*)(v + ((size_t)b * Nn + 2048) * Cc + i);
        vm = make_float4(0.f, 0.f, 0.f, 0.f);
    } else {
        vp = make_float4(0.f, 0.f, 0.f, 0.f);
        vm = vp;
    }
    size_t base = ((size_t)b * KF + k) * Cc + i;
    *(__half2*)(g_Vp + base)     = __half2{__float2half(vp.x), __float2half(vp.y)};
    *(__half2*)(g_Vp + base + 2) = __half2{__float2half(vp.z), __float2half(vp.w)};
    *(__half2*)(g_Vm + base)     = __half2{__float2half(vm.x), __float2half(vm.y)};
    *(__half2*)(g_Vm + base + 2) = __half2{__float2half(vm.z), __float2half(vm.w)};
}

// ---------------------------------------------------------------------------
// Forward WMMA GEMM. CTA 128(m) x 256(i), 512 threads, warp tile 32x64.
// 4-stage cp.async. Epilogue converts to fp16 -> g_Fre16/g_Fim16.
// Stage (27136B): A[128][40] @0 (10240B), B[32][264] @10240 (16896B)
// grid: (1, 8, 32); y>=4 -> sin/vm comp.
// ---------------------------------------------------------------------------
#define STAGE 27136

__global__ __launch_bounds__(512) void fwd_gemm() {
    extern __shared__ __align__(16) char sm[];
    const uint32_t sb = s2u(sm);
    const int tid = threadIdx.x;
    const int warp = tid >> 5, lane = tid & 31;
    const int wm = warp >> 2, wn = warp & 3;
    const int b = blockIdx.z;
    const int y = blockIdx.y;
    const int comp = (y >= 4) ? 1 : 0;
    const int yt = comp ? (y - 4) : y;

    const __half* Ap = comp ? g_Asin : g_Acos;
    const __half* Bp = comp ? g_Vm : g_Vp;
    __half* Fout = comp ? g_Fim16 : g_Fre16;
    const int row0 = yt * 128;
    const int NCH = KF / 32;

    FragC acc[2][4];
    #pragma unroll
    for (int a = 0; a < 2; a++)
        #pragma unroll
        for (int j = 0; j < 4; j++) wmma::fill_fragment(acc[a][j], 0.0f);

    const int ar = tid >> 2, aq = tid & 3;
    const int br = tid >> 4, bs = tid & 15;

    auto load = [&](int stage, int k0) {
        uint32_t s0 = sb + stage * STAGE;
        size_t ga = (size_t)(row0 + ar) * KF + k0 + aq * 8;
        CP16(s0 + ar * 80 + aq * 16, Ap + ga);
        size_t gb = ((size_t)b * KF + k0 + br) * Cc + bs * 8;
        uint32_t bd = s0 + 10240 + br * 528 + bs * 16;
        CP16(bd, Bp + gb);
        CP16(bd + 256, Bp + gb + 128);
        CP_COMMIT();
    };

    load(0, 0);
    load(1, 32);
    load(2, 64);

    int stage = 0;
    for (int c = 0; c < NCH; c++) {
        if (c + 3 < NCH) {
            int ns = stage + 3; if (ns >= 4) ns -= 4;
            load(ns, (c + 3) * 32);
            CP_WAIT3();
        } else if (c + 2 < NCH) {
            CP_WAIT2();
        } else if (c + 1 < NCH) {
            CP_WAIT1();
        } else {
            CP_WAIT0();
        }
        __syncthreads();

        const char* base = sm + stage * STAGE;
        const __half* As = (const __half*)(base);
        const __half* Bs = (const __half*)(base + 10240);

        #pragma unroll
        for (int ks = 0; ks < 2; ks++) {
            const int kk = ks * 16;
            FragB bf[4];
            #pragma unroll
            for (int j = 0; j < 4; j++)
                wmma::load_matrix_sync(bf[j], Bs + kk * 264 + wn * 64 + j * 16, 264);
            #pragma unroll
            for (int ms = 0; ms < 2; ms++) {
                FragA af;
                wmma::load_matrix_sync(af, As + (wm * 32 + ms * 16) * 40 + kk, 40);
                #pragma unroll
                for (int j = 0; j < 4; j++)
                    wmma::mma_sync(acc[ms][j], af, bf[j], acc[ms][j]);
            }
        }
        __syncthreads();
        stage++; if (stage >= 4) stage = 0;
    }

    // Epilogue: per-warp smem patch (16x68 fp32), convert to fp16, store.
    float* patch = (float*)sm + warp * 1088;   // 4352B each, 16*4352=69632 < smem
    #pragma unroll
    for (int ms = 0; ms < 2; ms++) {
        #pragma unroll
        for (int j = 0; j < 4; j++)
            wmma::store_matrix_sync(patch + j * 16, acc[ms][j], 68, wmma::mem_row_major);
        __syncwarp();
        int mrow = row0 + wm * 32 + ms * 16;
        #pragma unroll
        for (int rr = 0; rr < 16; rr++) {
            float x0 = patch[rr * 68 + lane * 2];
            float x1 = patch[rr * 68 + lane * 2 + 1];
            *(__half2*)(Fout + ((size_t)b * Mm + mrow + rr) * Cc + wn * 64 + lane * 2)
                = __half2{__float2half(x0), __float2half(x1)};
        }
        __syncwarp();
    }
}

// ---------------------------------------------------------------------------
// Mid WMMA: for each mode m, G[32b, 256o] = F[32b, 256i] @ R16[m] (re & im).
// 256 threads, 8 warps; warp tile 32(b) x 32(o). K=256, B pipelined 4x32.
// A (F fp16) loaded via cp.async (its group drains at the first WAIT3).
// smem: A_re[32][264] @0 (16896), A_im @16896, B stages @33792 (+s*16896)
// ---------------------------------------------------------------------------
#define MAST 16896
#define MBOFF 33792

__global__ __launch_bounds__(256) void mid_wmma() {
    extern __shared__ __align__(16) char sm[];
    const uint32_t sb = s2u(sm);
    const int tid = threadIdx.x;
    const int warp = tid >> 5, lane = tid & 31;
    const int m = blockIdx.x;

    __half* Are = (__half*)sm;
    __half* Aim = (__half*)(sm + MAST);

    // A loader: 2048 CP16 over 256 threads (F fp16, both comps).
    #pragma unroll
    for (int it = 0; it < 8; it++) {
        int idx = tid + 256 * it;
        int plane = idx >> 10, rem = idx & 1023;
        int row = rem >> 5, seg = rem & 31;
        const __half* src = (plane ? g_Fim16 : g_Fre16)
                            + ((size_t)row * Mm + m) * Cc + seg * 8;
        uint32_t dst = sb + plane * MAST + row * 528 + seg * 16;
        CP16(dst, src);
    }
    CP_COMMIT();

    const int kr = tid >> 3, seg = tid & 7;
    auto loadB = [&](int stage, int c) {
        uint32_t s0 = sb + MBOFF + stage * MAST;
        size_t gb = ((size_t)m * Cc + c * 32 + kr) * Cc + seg * 32;
        uint32_t bd = s0 + kr * 528 + seg * 64;
        CP16(bd,      g_R16 + gb);
        CP16(bd + 16, g_R16 + gb + 8);
        CP16(bd + 32, g_R16 + gb + 16);
        CP16(bd + 48, g_R16 + gb + 24);
        CP_COMMIT();
    };

    loadB(0, 0);
    loadB(1, 1);
    loadB(2, 2);

    FragC accR[2][2], accI[2][2];
    #pragma unroll
    for (int a = 0; a < 2; a++)
        #pragma unroll
        for (int j = 0; j < 2; j++) {
            wmma::fill_fragment(accR[a][j], 0.0f);
            wmma::fill_fragment(accI[a][j], 0.0f);
        }

    int stage = 0;
    for (int c = 0; c < 8; c++) {
        if (c + 3 < 8) {
            int ns = stage + 3; if (ns >= 4) ns -= 4;
            loadB(ns, c + 3);
            CP_WAIT3();
        } else if (c + 2 < 8) {
            CP_WAIT2();
        } else if (c + 1 < 8) {
            CP_WAIT1();
        } else {
            CP_WAIT0();
        }
        __syncthreads();

        const __half* Bs = (const __half*)(sm + MBOFF + stage * MAST);
        #pragma unroll
        for (int ks = 0; ks < 2; ks++) {
            const int kk = c * 32 + ks * 16;
            FragB bf[2];
            #pragma unroll
            for (int j = 0; j < 2; j++)
                wmma::load_matrix_sync(bf[j], Bs + (ks * 16) * 264 + warp * 32 + j * 16, 264);
            #pragma unroll
            for (int ms = 0; ms < 2; ms++) {
                FragA ar_, ai_;
                wmma::load_matrix_sync(ar_, Are + ms * 16 * 264 + kk, 264);
                wmma::load_matrix_sync(ai_, Aim + ms * 16 * 264 + kk, 264);
                #pragma unroll
                for (int j = 0; j < 2; j++) {
                    wmma::mma_sync(accR[ms][j], ar_, bf[j], accR[ms][j]);
                    wmma::mma_sync(accI[ms][j], ai_, bf[j], accI[ms][j]);
                }
            }
        }
        __syncthreads();
        stage++; if (stage >= 4) stage = 0;
    }

    // Epilogue: bounce -> fp16 planes, coalesced row writes.
    float* bre = (float*)(sm + MBOFF) + warp * 2560;
    float* bim = bre + 1280;
    #pragma unroll
    for (int ms = 0; ms < 2; ms++)
        #pragma unroll
        for (int j = 0; j < 2; j++) {
            wmma::store_matrix_sync(bre + ms * 16 * 40 + j * 16, accR[ms][j], 40, wmma::mem_row_major);
            wmma::store_matrix_sync(bim + ms * 16 * 40 + j * 16, accI[ms][j], 40, wmma::mem_row_major);
        }
    __syncwarp();
    #pragma unroll 4
    for (int r = 0; r < 32; r++) {
        size_t g = ((size_t)r * Mm + m) * Cc + warp * 32 + lane;
        g_Gre16[g] = __float2half(bre[r * 40 + lane]);
        g_Gim16[g] = __float2half(bim[r * 40 + lane]);
    }
}

// ---------------------------------------------------------------------------
// Inverse WMMA GEMM with fused combine. CTA 128(n) x 128(o), 512 threads.
// Warps 0-7: C = cos @ Gre.  Warps 8-15: S = sin @ Gim.  (warp tile 32x64)
// Epilogue: out[n] = v[n] + C - S;  out[N-n] = v[N-n] + C + S.
// Stage (37888B): Acos[128][40] @0, Asin @10240, BGre[32][136] @20480, BGim @29184
// 3 stages = 113664; epilogue Cbuf/Sbuf 2x128x132 fp32 = 135168 (smem size).
// grid: (2, 16, 32)
// ---------------------------------------------------------------------------
#define ISTAGE 37888

__global__ __launch_bounds__(512) void inv_gemm(const float* __restrict__ v,
                                                float* __restrict__ out) {
    extern __shared__ __align__(16) char sm[];
    const uint32_t sb = s2u(sm);
    const int tid = threadIdx.x;
    const int warp = tid >> 5;
    const int comp = warp >> 3;          // 0: C (cos,Gre)   1: S (sin,Gim)
    const int w8 = warp & 7;
    const int wm = w8 >> 1, wn = w8 & 1; // warp tile 32 rows x 64 cols
    const int colt = blockIdx.x, yt = blockIdx.y, b = blockIdx.z;
    const int row0 = yt * 128, c0 = colt * 128;
    const int NCH = Mm / 32;             // 16

    FragC acc[2][4];
    #pragma unroll
    for (int a = 0; a < 2; a++)
        #pragma unroll
        for (int j = 0; j < 4; j++) wmma::fill_fragment(acc[a][j], 0.0f);

    const int ar = tid >> 2, aq = tid & 3;   // A: 128 rows x 4 quads, both planes
    const int br = tid >> 4, bs = tid & 15;  // B: 32 rows x 16 segs, both planes

    auto load = [&](int stage, int k0) {
        uint32_t s0 = sb + stage * ISTAGE;
        size_t ga = (size_t)(row0 + ar) * Mm + k0 + aq * 8;
        uint32_t ad = s0 + ar * 80 + aq * 16;
        CP16(ad,         g_icos + ga);
        CP16(ad + 10240, g_isin + ga);
        size_t gb = ((size_t)b * Mm + k0 + br) * Cc + c0 + bs * 8;
        uint32_t bd = s0 + 20480 + br * 272 + bs * 16;
        CP16(bd,        g_Gre16 + gb);
        CP16(bd + 8704, g_Gim16 + gb);
        CP_COMMIT();
    };

    load(0, 0);
    load(1, 32);

    int stage = 0;
    for (int c = 0; c < NCH; c++) {
        if (c + 2 < NCH) {
            int ns = stage + 2; if (ns >= 3) ns -= 3;
            load(ns, (c + 2) * 32);
            CP_WAIT2();
        } else if (c + 1 < NCH) {
            CP_WAIT1();
        } else {
            CP_WAIT0();
        }
        __syncthreads();

        const char* base = sm + stage * ISTAGE;
        const __half* As = (const __half*)(base + comp * 10240);
        const __half* Bs = (const __half*)(base + 20480 + comp * 8704);

        #pragma unroll
        for (int ks = 0; ks < 2; ks++) {
            const int kk = ks * 16;
            FragB bf[4];
            #pragma unroll
            for (int j = 0; j < 4; j++)
                wmma::load_matrix_sync(bf[j], Bs + kk * 136 + wn * 64 + j * 16, 136);
            #pragma unroll
            for (int ms = 0; ms < 2; ms++) {
                FragA af;
                wmma::load_matrix_sync(af, As + (wm * 32 + ms * 16) * 40 + kk, 40);
                #pragma unroll
                for (int j = 0; j < 4; j++)
                    wmma::mma_sync(acc[ms][j], af, bf[j], acc[ms][j]);
            }
        }
        __syncthreads();
        stage++; if (stage >= 3) stage = 0;
    }

    // Epilogue: C and S to smem, then fused combine with v.
    float* Cbuf = (float*)sm;
    float* Sbuf = Cbuf + 128 * 132;
    float* buf = comp ? Sbuf : Cbuf;
    #pragma unroll
    for (int ms = 0; ms < 2; ms++)
        #pragma unroll
        for (int j = 0; j < 4; j++)
            wmma::store_matrix_sync(buf + (wm * 32 + ms * 16) * 132 + wn * 64 + j * 16,
                                    acc[ms][j], 132, wmma::mem_row_major);
    __syncthreads();

    #pragma unroll
    for (int it = 0; it < 8; it++) {
        int idx = tid + 512 * it;            // 0..4095 (128 rows x 32 float4)
        int r = idx >> 5, c4 = idx & 31;
        float4 C = *(const float4*)(Cbuf + r * 132 + c4 * 4);
        float4 S = *(const float4*)(Sbuf + r * 132 + c4 * 4);
        int n = row0 + r;
        int o = c0 + c4 * 4;
        size_t i1 = ((size_t)b * Nn + n) * Cc + o;
        float4 v1 = *(const float4*)(v + i1);
        *(float4*)(out + i1) = make_float4(v1.x + C.x - S.x, v1.y + C.y - S.y,
                                           v1.z + C.z - S.z, v1.w + C.w - S.w);
        if (n > 0) {
            size_t i2 = ((size_t)b * Nn + (Nn - n)) * Cc + o;
            float4 v2 = *(const float4*)(v + i2);
            *(float4*)(out + i2) = make_float4(v2.x + C.x + S.x, v2.y + C.y + S.y,
                                               v2.z + C.z + S.z, v2.w + C.w + S.w);
        }
    }
}

// out[b,2048,o] = v[b,2048,o] + sum_m (-1)^m * Gre'[b,m,o]   (reads fp16 Gre)
__global__ __launch_bounds__(64) void row2048(const float* __restrict__ v,
                                              float* __restrict__ out) {
    const int b = blockIdx.x;
    const int o = threadIdx.x * 4;
    float acc0 = 0.f, acc1 = 0.f, acc2 = 0.f, acc3 = 0.f;
    #pragma unroll 8
    for (int m = 0; m < Mm; m++) {
        float sgn = (m & 1) ? -1.0f : 1.0f;
        const __half* g = g_Gre16 + ((size_t)b * Mm + m) * Cc + o;
        __half2 a = *(const __half2*)(g);
        __half2 bb = *(const __half2*)(g + 2);
        acc0 += sgn * __half2float(a.x);
        acc1 += sgn * __half2float(a.y);
        acc2 += sgn * __half2float(bb.x);
        acc3 += sgn * __half2float(bb.y);
    }
    size_t idx = ((size_t)b * Nn + 2048) * Cc + o;
    float4 vv = *(const float4*)(v + idx);
    *(float4*)(out + idx) = make_float4(vv.x + acc0, vv.y + acc1,
                                        vv.z + acc2, vv.w + acc3);
}

// ---------------------------------------------------------------------------
extern "C" void kernel_launch(void* const* d_in, const int* in_sizes, int n_in,
                              void* d_out, int out_size) {
    const float* v = (const float*)d_in[0];
    const float* R = (const float*)d_in[1];
    float* out = (float*)d_out;

    const int smF = 4 * STAGE;       // 108544
    const int smMid = 115712;
    const int smInv = 135168;
    cudaFuncSetAttribute(fwd_gemm, cudaFuncAttributeMaxDynamicSharedMemorySize, smF);
    cudaFuncSetAttribute(mid_wmma, cudaFuncAttributeMaxDynamicSharedMemorySize, smMid);
    cudaFuncSetAttribute(inv_gemm, cudaFuncAttributeMaxDynamicSharedMemorySize, smInv);

    pack_R<<<(int)(((size_t)Mm * Cc * Cc / 4 + 255) / 256), 256>>>(R);
    genA_fwd<<<(Mm * KF) / 256, 256>>>();
    genA_inv<<<(NH * Mm) / 256, 256>>>();
    packVpVm<<<(int)(((size_t)Bb * KF * 64 + 255) / 256), 256>>>(v);
    fwd_gemm<<<dim3(1, 8, Bb), 512, smF>>>();
    mid_wmma<<<Mm, 256, smMid>>>();
    inv_gemm<<<dim3(2, 16, Bb), 512, smInv>>>(v, out);
    row2048<<<Bb, 64>>>(v, out);
}